// round 2
// baseline (speedup 1.0000x reference)
#include <cuda_runtime.h>
#include <math.h>

#define NN 100000
#define NE 3200000
#define NGR 64
static __device__ __constant__ float AVG_LOG_C = 3.4965076f; // log(33.0)

// ---------------- scratch (device globals; no allocations) ----------------
__device__ int   g_cnt[NN];
__device__ int   g_fill[NN];
__device__ int   g_rowstart[NN];
__device__ int   g_bsum[512];
__device__ int   g_boff[512];
__device__ int   g_srt[NE];
__device__ float g_s1[NN];
__device__ float g_s2[NN];
__device__ float g_hA[NN * 96];
__device__ float g_hB[NN * 96];
__device__ float g_agg[NN * 384];
__device__ float g_bnsum[128];
__device__ float g_bnssq[128];
__device__ float g_scale[128];
__device__ float g_shift[128];
__device__ float g_zsum[NGR * 20];
__device__ int   g_gcnt[NGR];

// ---------------- f32x2 packed helpers ----------------
__device__ __forceinline__ unsigned long long pk2(float lo, float hi) {
    unsigned long long r;
    asm("mov.b64 %0, {%1, %2};" : "=l"(r) : "f"(lo), "f"(hi));
    return r;
}
__device__ __forceinline__ void fma2(unsigned long long& d, unsigned long long a, unsigned long long b) {
    asm("fma.rn.f32x2 %0, %1, %2, %0;" : "+l"(d) : "l"(a), "l"(b));
}
__device__ __forceinline__ float2 unpk(unsigned long long v) {
    float2 r;
    asm("mov.b64 {%0, %1}, %2;" : "=f"(r.x), "=f"(r.y) : "l"(v));
    return r;
}

// ---------------- graph preprocessing ----------------
__global__ void k_zero() {
    int i = blockIdx.x * 256 + threadIdx.x;
    if (i < NN) { g_cnt[i] = 0; g_fill[i] = 0; }
    if (i < NGR * 20) g_zsum[i] = 0.f;
    if (i < NGR) g_gcnt[i] = 0;
}

__global__ void k_count(const int* __restrict__ dst) {
    int i = blockIdx.x * 256 + threadIdx.x;
    if (i < NE) atomicAdd(&g_cnt[dst[i]], 1);
}

__global__ void k_scan1() {
    __shared__ int s[256];
    int tid = threadIdx.x;
    int i = blockIdx.x * 256 + tid;
    s[tid] = (i < NN) ? g_cnt[i] : 0;
    __syncthreads();
    for (int off = 128; off > 0; off >>= 1) {
        if (tid < off) s[tid] += s[tid + off];
        __syncthreads();
    }
    if (tid == 0) g_bsum[blockIdx.x] = s[0];
}

__global__ void k_scan2() {
    __shared__ int s[512];
    int tid = threadIdx.x;
    int v = (tid < 391) ? g_bsum[tid] : 0;
    s[tid] = v;
    __syncthreads();
    for (int off = 1; off < 512; off <<= 1) {
        int t = (tid >= off) ? s[tid - off] : 0;
        __syncthreads();
        s[tid] += t;
        __syncthreads();
    }
    g_boff[tid] = s[tid] - v;
}

__global__ void k_scan3() {
    __shared__ int s[256];
    int tid = threadIdx.x;
    int i = blockIdx.x * 256 + tid;
    int v = (i < NN) ? g_cnt[i] : 0;
    s[tid] = v;
    __syncthreads();
    for (int off = 1; off < 256; off <<= 1) {
        int t = (tid >= off) ? s[tid - off] : 0;
        __syncthreads();
        s[tid] += t;
        __syncthreads();
    }
    if (i < NN) g_rowstart[i] = g_boff[blockIdx.x] + s[tid] - v;
}

__global__ void k_scatter(const int* __restrict__ src, const int* __restrict__ dst) {
    int i = blockIdx.x * 256 + threadIdx.x;
    if (i < NE) {
        int d = dst[i];
        int p = g_rowstart[d] + atomicAdd(&g_fill[d], 1);
        g_srt[p] = src[i];
    }
}

__global__ void k_prep() {
    int i = blockIdx.x * 256 + threadIdx.x;
    if (i < NN) {
        int deg = g_cnt[i];
        float degc = (float)(deg > 1 ? deg : 1);
        float logd = logf(degc + 1.f);
        g_s1[i] = logd / AVG_LOG_C;
        g_s2[i] = AVG_LOG_C / logd;
    }
}

// ---------------- per-node segmented aggregation (warp per node) ----------------
template <int F>
__global__ void __launch_bounds__(256) k_agg(const float* __restrict__ H) {
    constexpr int FPT = F / 32;
    int wid = (blockIdx.x * 256 + threadIdx.x) >> 5;
    int lane = threadIdx.x & 31;
    if (wid >= NN) return;
    int n = wid;
    int deg = g_cnt[n];
    int st = g_rowstart[n];
    float sum[FPT], ssq[FPT], mn[FPT], mx[FPT];
#pragma unroll
    for (int i = 0; i < FPT; i++) { sum[i] = 0.f; ssq[i] = 0.f; mn[i] = 3.4e38f; mx[i] = -3.4e38f; }
    int e = 0;
    // 4-edge unrolled body for memory-level parallelism against L2 latency
    for (; e + 4 <= deg; e += 4) {
        int s0 = g_srt[st + e + 0];
        int s1 = g_srt[st + e + 1];
        int s2 = g_srt[st + e + 2];
        int s3 = g_srt[st + e + 3];
        const float* r0 = H + s0 * F;
        const float* r1 = H + s1 * F;
        const float* r2 = H + s2 * F;
        const float* r3 = H + s3 * F;
#pragma unroll
        for (int i = 0; i < FPT; i++) {
            int f = lane + 32 * i;
            float v0 = r0[f], v1 = r1[f], v2 = r2[f], v3 = r3[f];
            sum[i] += v0 + v1 + v2 + v3;
            ssq[i] += v0 * v0 + v1 * v1 + v2 * v2 + v3 * v3;
            mn[i] = fminf(mn[i], fminf(fminf(v0, v1), fminf(v2, v3)));
            mx[i] = fmaxf(mx[i], fmaxf(fmaxf(v0, v1), fmaxf(v2, v3)));
        }
    }
    for (; e < deg; e++) {
        int s = g_srt[st + e];
        const float* row = H + s * F;
#pragma unroll
        for (int i = 0; i < FPT; i++) {
            float v = row[lane + 32 * i];
            sum[i] += v;
            ssq[i] += v * v;
            mn[i] = fminf(mn[i], v);
            mx[i] = fmaxf(mx[i], v);
        }
    }
    float inv = 1.f / (float)(deg > 1 ? deg : 1);
    float* out = g_agg + n * (4 * F);
#pragma unroll
    for (int i = 0; i < FPT; i++) {
        int f = lane + 32 * i;
        float mean = sum[i] * inv;
        float msq = ssq[i] * inv;
        float sd = sqrtf(fmaxf(msq - mean * mean, 0.f) + 1e-5f);
        float lmn = (deg > 0) ? mn[i] : 0.f;
        float lmx = (deg > 0) ? mx[i] : 0.f;
        out[f] = mean;
        out[F + f] = lmn;
        out[2 * F + f] = lmx;
        out[3 * F + f] = sd;
    }
}

// ---------------- fused PNA GEMM v2 (f32x2 packed FMA) ----------------
// 128 nodes x FO per block, 256 threads: 16 col-groups x 16 node-groups(8 nodes).
// K-order permuted: row k<F = self feature; k>=F: j=k-F, jj=j/3, scaler=j%3
// (W rows permuted identically -> same dot product).
// A tile stored kk-major with XOR swizzle to keep both build-stores and
// main-loop loads cheap; global build reads are coalesced along k.
template <int F, int FO, int CPT, bool RELU>
__global__ void __launch_bounds__(256, 2) k_gemm2(const float* __restrict__ H,
                                                  const float* __restrict__ W,
                                                  const float* __restrict__ B,
                                                  float* __restrict__ OUT) {
    constexpr int K = 13 * F;
    constexpr int FOP = 16 * CPT;
    constexpr int F4 = 4 * F;
    constexpr int NP = CPT / 2;
    __shared__ float As[32 * 128];
    __shared__ float Ws[32 * FOP];
    int tid = threadIdx.x;
    int ct = tid & 15;
    int nt = tid >> 4;
    int n0 = blockIdx.x * 128;
    int nodeb = tid & 127;
    int kkb = tid >> 7;       // 0 or 1
    int nglob = n0 + nodeb;
    bool nvalid = nglob < NN;
    int nclamp = nvalid ? nglob : 0;
    float s1 = g_s1[nclamp];
    float s2 = g_s2[nclamp];
    const float* Hrow = H + (size_t)nclamp * F;
    const float* Arow = g_agg + (size_t)nclamp * F4;

    unsigned long long acc[4][CPT];
#pragma unroll
    for (int s = 0; s < 4; s++)
#pragma unroll
        for (int c = 0; c < CPT; c++) acc[s][c] = 0ull;

    for (int kt = 0; kt < K; kt += 32) {
        // ---- W tile (permuted row order), coalesced, zero-padded cols ----
        for (int idx = tid; idx < 32 * FOP; idx += 256) {
            int kk = idx / FOP;
            int c = idx - kk * FOP;
            float v = 0.f;
            if (c < FO) {
                int k = kt + kk;
                int wrow;
                if (k < F) wrow = k;
                else {
                    int j = k - F;
                    int jj = j / 3;
                    int r = j - 3 * jj;
                    wrow = F + r * F4 + jj;
                }
                v = W[wrow * FO + c];
            }
            Ws[idx] = v;
        }
        // ---- A tile build: thread owns one node, kk = kkb + 2t ----
#pragma unroll
        for (int t = 0; t < 16; t++) {
            int kk = kkb + 2 * t;
            int k = kt + kk;
            float v = 0.f;
            if (nvalid) {
                if (k < F) {
                    v = Hrow[k];
                } else {
                    int j = k - F;
                    int jj = j / 3;
                    int r = j - 3 * jj;
                    float sc = (r == 0) ? 1.f : ((r == 1) ? s1 : s2);
                    v = Arow[jj] * sc;
                }
            }
            As[kk * 128 + (nodeb ^ ((kk & 15) * 2))] = v;
        }
        __syncthreads();
        // ---- main loop: packed f32x2 FMA ----
#pragma unroll 8
        for (int kk = 0; kk < 32; kk++) {
            int sw = (kk & 15) * 2;
            const float* Ak = As + kk * 128;
            unsigned long long ap[4];
#pragma unroll
            for (int s = 0; s < 4; s++)
                ap[s] = *(const unsigned long long*)&Ak[(nt * 8 + 2 * s) ^ sw];
            const float* Wk = Ws + kk * FOP + ct * CPT;
#pragma unroll
            for (int j = 0; j < NP; j++) {
                float2 w2 = *(const float2*)&Wk[2 * j];
                unsigned long long wa = pk2(w2.x, w2.x);
                unsigned long long wb = pk2(w2.y, w2.y);
#pragma unroll
                for (int s = 0; s < 4; s++) {
                    fma2(acc[s][2 * j], ap[s], wa);
                    fma2(acc[s][2 * j + 1], ap[s], wb);
                }
            }
        }
        __syncthreads();
    }
    // ---- epilogue ----
#pragma unroll
    for (int c = 0; c < CPT; c++) {
        int col = ct * CPT + c;
        if (col < FO) {
            float bias = B[col];
#pragma unroll
            for (int s = 0; s < 4; s++) {
                float2 v = unpk(acc[s][c]);
                int n = n0 + nt * 8 + 2 * s;
                float ra = v.x + bias;
                float rb = v.y + bias;
                if (RELU) { ra = fmaxf(ra, 0.f); rb = fmaxf(rb, 0.f); }
                if (n < NN) OUT[(size_t)n * FO + col] = ra;
                if (n + 1 < NN) OUT[(size_t)(n + 1) * FO + col] = rb;
            }
        }
    }
}

// ---------------- batchnorm ----------------
__global__ void k_bnzero() {
    int i = threadIdx.x;
    if (i < 128) { g_bnsum[i] = 0.f; g_bnssq[i] = 0.f; }
}

template <int C>
__global__ void k_bnstats(const float* __restrict__ h) {
    int c = threadIdx.x;
    if (c >= C) return;
    float s = 0.f, q = 0.f;
    for (int r = blockIdx.x; r < NN; r += gridDim.x) {
        float v = h[(size_t)r * C + c];
        s += v;
        q += v * v;
    }
    atomicAdd(&g_bnsum[c], s);
    atomicAdd(&g_bnssq[c], q);
}

template <int C>
__global__ void k_bnfin(const float* __restrict__ g, const float* __restrict__ be) {
    int c = threadIdx.x;
    if (c < C) {
        float mu = g_bnsum[c] / (float)NN;
        float var = g_bnssq[c] / (float)NN - mu * mu;
        float rs = rsqrtf(var + 1e-5f);
        float sc = g[c] * rs;
        g_scale[c] = sc;
        g_shift[c] = be[c] - mu * sc;
    }
}

template <int C, bool RELU>
__global__ void k_bnapply(float* __restrict__ h) {
    int i = blockIdx.x * 256 + threadIdx.x;
    if (i < NN * C) {
        int c = i % C;
        float v = h[i] * g_scale[c] + g_shift[c];
        if (RELU) v = fmaxf(v, 0.f);
        h[i] = v;
    }
}

// ---------------- pooling + head ----------------
__global__ void k_pool(const float* __restrict__ h, const int* __restrict__ batch) {
    int i = blockIdx.x * 256 + threadIdx.x;
    if (i < NN) {
        int g = batch[i];
        atomicAdd(&g_gcnt[g], 1);
        const float* row = h + (size_t)i * 20;
#pragma unroll
        for (int c = 0; c < 20; c++) {
            float v = row[c] * g_scale[c] + g_shift[c];
            atomicAdd(&g_zsum[g * 20 + c], v);
        }
    }
}

__global__ void k_final(const float* __restrict__ wl, const float* __restrict__ bl,
                        float* __restrict__ out, int out_size) {
    int g = threadIdx.x;
    if (g >= NGR) return;
    float inv = 1.f / fmaxf((float)g_gcnt[g], 1.f);
    float z[20];
#pragma unroll
    for (int c = 0; c < 20; c++) z[c] = g_zsum[g * 20 + c] * inv;
    float lo[11];
    float m = -3.4e38f;
#pragma unroll
    for (int o = 0; o < 11; o++) {
        float a = bl[o];
#pragma unroll
        for (int c = 0; c < 20; c++) a += z[c] * wl[c * 11 + o];
        lo[o] = a;
        m = fmaxf(m, a);
    }
    float ssum = 0.f;
#pragma unroll
    for (int o = 0; o < 11; o++) { lo[o] = expf(lo[o] - m); ssum += lo[o]; }
    float isum = 1.f / ssum;
#pragma unroll
    for (int o = 0; o < 11; o++) {
        int idx = g * 11 + o;
        if (idx < out_size) out[idx] = lo[o] * isum;
    }
#pragma unroll
    for (int c = 0; c < 20; c++) {
        int idx = NGR * 11 + g * 20 + c;
        if (idx < out_size) out[idx] = z[c];
    }
}

// ---------------- launcher ----------------
extern "C" void kernel_launch(void* const* d_in, const int* in_sizes, int n_in,
                              void* d_out, int out_size) {
    const float* x = (const float*)d_in[0];
    const int* ei = (const int*)d_in[1];
    const int* src = ei;
    const int* dst = ei + NE;
    const int* batch = (const int*)d_in[2];
    const float* w0 = (const float*)d_in[3];  const float* b0 = (const float*)d_in[4];
    const float* w1 = (const float*)d_in[5];  const float* b1 = (const float*)d_in[6];
    const float* w2 = (const float*)d_in[7];  const float* b2 = (const float*)d_in[8];
    const float* w3 = (const float*)d_in[9];  const float* b3 = (const float*)d_in[10];
    const float* g0 = (const float*)d_in[11]; const float* be0 = (const float*)d_in[12];
    const float* g1 = (const float*)d_in[13]; const float* be1 = (const float*)d_in[14];
    const float* g2 = (const float*)d_in[15]; const float* be2 = (const float*)d_in[16];
    const float* wl = (const float*)d_in[17]; const float* bl = (const float*)d_in[18];

    void* pA = 0; void* pB = 0;
    cudaGetSymbolAddress(&pA, g_hA);
    cudaGetSymbolAddress(&pB, g_hB);
    float* hA = (float*)pA;
    float* hB = (float*)pB;

    const int GB_E = (NE + 255) / 256;
    const int GB_N = (NN + 255) / 256;
    const int GB_G = (NN + 127) / 128;   // 782 blocks for gemm v2

    k_zero<<<GB_N, 256>>>();
    k_count<<<GB_E, 256>>>(dst);
    k_scan1<<<GB_N, 256>>>();
    k_scan2<<<1, 512>>>();
    k_scan3<<<GB_N, 256>>>();
    k_scatter<<<GB_E, 256>>>(src, dst);
    k_prep<<<GB_N, 256>>>();

    // layer 0: 64 -> 96, BN + relu
    k_agg<64><<<(NN * 32 + 255) / 256, 256>>>(x);
    k_gemm2<64, 96, 6, false><<<GB_G, 256>>>(x, w0, b0, hA);
    k_bnzero<<<1, 128>>>();
    k_bnstats<96><<<512, 96>>>(hA);
    k_bnfin<96><<<1, 96>>>(g0, be0);
    k_bnapply<96, true><<<(NN * 96 + 255) / 256, 256>>>(hA);

    // layer 1: 96 -> 64, BN + relu
    k_agg<96><<<(NN * 32 + 255) / 256, 256>>>(hA);
    k_gemm2<96, 64, 4, false><<<GB_G, 256>>>(hA, w1, b1, hB);
    k_bnzero<<<1, 128>>>();
    k_bnstats<64><<<512, 64>>>(hB);
    k_bnfin<64><<<1, 64>>>(g1, be1);
    k_bnapply<64, true><<<(NN * 64 + 255) / 256, 256>>>(hB);

    // layer 2: 64 -> 32, relu fused in epilogue
    k_agg<64><<<(NN * 32 + 255) / 256, 256>>>(hB);
    k_gemm2<64, 32, 2, true><<<GB_G, 256>>>(hB, w2, b2, hA);

    // layer 3: 32 -> 20, BN affine fused into pooling
    k_agg<32><<<(NN * 32 + 255) / 256, 256>>>(hA);
    k_gemm2<32, 20, 2, false><<<GB_G, 256>>>(hA, w3, b3, hB);
    k_bnzero<<<1, 128>>>();
    k_bnstats<20><<<512, 32>>>(hB);
    k_bnfin<20><<<1, 32>>>(g2, be2);

    k_pool<<<GB_N, 256>>>(hB, batch);
    k_final<<<1, 64>>>(wl, bl, (float*)d_out, out_size);
}

// round 3
// speedup vs baseline: 1.3229x; 1.3229x over previous
#include <cuda_runtime.h>
#include <math.h>

#define NN 100000
#define NE 3200000
#define NGR 64
static __device__ __constant__ float AVG_LOG_C = 3.4965076f; // log(33.0)

// ---------------- scratch (device globals; no allocations) ----------------
__device__ int   g_cnt[NN];
__device__ int   g_fill[NN];
__device__ int   g_rowstart[NN];
__device__ int   g_bsum[512];
__device__ int   g_boff[512];
__device__ int   g_srt[NE];
__device__ float g_s1[NN];
__device__ float g_s2[NN];
__device__ float g_hA[NN * 96];
__device__ float g_hB[NN * 96];
__device__ float g_agg[NN * 384];
__device__ float g_bnsum[128];
__device__ float g_bnssq[128];
__device__ float g_scale[128];
__device__ float g_shift[128];
__device__ float g_zsum[NGR * 20];
__device__ int   g_gcnt[NGR];

// ---------------- f32x2 packed helpers ----------------
__device__ __forceinline__ unsigned long long pk2(float lo, float hi) {
    unsigned long long r;
    asm("mov.b64 %0, {%1, %2};" : "=l"(r) : "f"(lo), "f"(hi));
    return r;
}
__device__ __forceinline__ void fma2(unsigned long long& d, unsigned long long a, unsigned long long b) {
    asm("fma.rn.f32x2 %0, %1, %2, %0;" : "+l"(d) : "l"(a), "l"(b));
}
__device__ __forceinline__ float2 unpk(unsigned long long v) {
    float2 r;
    asm("mov.b64 {%0, %1}, %2;" : "=f"(r.x), "=f"(r.y) : "l"(v));
    return r;
}

// ---------------- graph preprocessing ----------------
__global__ void k_zero() {
    int i = blockIdx.x * 256 + threadIdx.x;
    if (i < NN) { g_cnt[i] = 0; g_fill[i] = 0; }
    if (i < NGR * 20) g_zsum[i] = 0.f;
    if (i < NGR) g_gcnt[i] = 0;
}

__global__ void k_count(const int* __restrict__ dst) {
    int i = blockIdx.x * 256 + threadIdx.x;
    if (i < NE) atomicAdd(&g_cnt[dst[i]], 1);
}

__global__ void k_scan1() {
    __shared__ int s[256];
    int tid = threadIdx.x;
    int i = blockIdx.x * 256 + tid;
    s[tid] = (i < NN) ? g_cnt[i] : 0;
    __syncthreads();
    for (int off = 128; off > 0; off >>= 1) {
        if (tid < off) s[tid] += s[tid + off];
        __syncthreads();
    }
    if (tid == 0) g_bsum[blockIdx.x] = s[0];
}

__global__ void k_scan2() {
    __shared__ int s[512];
    int tid = threadIdx.x;
    int v = (tid < 391) ? g_bsum[tid] : 0;
    s[tid] = v;
    __syncthreads();
    for (int off = 1; off < 512; off <<= 1) {
        int t = (tid >= off) ? s[tid - off] : 0;
        __syncthreads();
        s[tid] += t;
        __syncthreads();
    }
    g_boff[tid] = s[tid] - v;
}

__global__ void k_scan3() {
    __shared__ int s[256];
    int tid = threadIdx.x;
    int i = blockIdx.x * 256 + tid;
    int v = (i < NN) ? g_cnt[i] : 0;
    s[tid] = v;
    __syncthreads();
    for (int off = 1; off < 256; off <<= 1) {
        int t = (tid >= off) ? s[tid - off] : 0;
        __syncthreads();
        s[tid] += t;
        __syncthreads();
    }
    if (i < NN) g_rowstart[i] = g_boff[blockIdx.x] + s[tid] - v;
}

__global__ void k_scatter(const int* __restrict__ src, const int* __restrict__ dst) {
    int i = blockIdx.x * 256 + threadIdx.x;
    if (i < NE) {
        int d = dst[i];
        int p = g_rowstart[d] + atomicAdd(&g_fill[d], 1);
        g_srt[p] = src[i];
    }
}

__global__ void k_prep() {
    int i = blockIdx.x * 256 + threadIdx.x;
    if (i < NN) {
        int deg = g_cnt[i];
        float degc = (float)(deg > 1 ? deg : 1);
        float logd = logf(degc + 1.f);
        g_s1[i] = logd / AVG_LOG_C;
        g_s2[i] = AVG_LOG_C / logd;
    }
}

// ---------------- per-node segmented aggregation (warp per node) ----------------
template <int F>
__global__ void __launch_bounds__(256) k_agg(const float* __restrict__ H) {
    constexpr int FPT = F / 32;
    int wid = (blockIdx.x * 256 + threadIdx.x) >> 5;
    int lane = threadIdx.x & 31;
    if (wid >= NN) return;
    int n = wid;
    int deg = g_cnt[n];
    int st = g_rowstart[n];
    float sum[FPT], ssq[FPT], mn[FPT], mx[FPT];
#pragma unroll
    for (int i = 0; i < FPT; i++) { sum[i] = 0.f; ssq[i] = 0.f; mn[i] = 3.4e38f; mx[i] = -3.4e38f; }
    int e = 0;
    for (; e + 4 <= deg; e += 4) {
        int s0 = g_srt[st + e + 0];
        int s1 = g_srt[st + e + 1];
        int s2 = g_srt[st + e + 2];
        int s3 = g_srt[st + e + 3];
        const float* r0 = H + s0 * F;
        const float* r1 = H + s1 * F;
        const float* r2 = H + s2 * F;
        const float* r3 = H + s3 * F;
#pragma unroll
        for (int i = 0; i < FPT; i++) {
            int f = lane + 32 * i;
            float v0 = r0[f], v1 = r1[f], v2 = r2[f], v3 = r3[f];
            sum[i] += v0 + v1 + v2 + v3;
            ssq[i] += v0 * v0 + v1 * v1 + v2 * v2 + v3 * v3;
            mn[i] = fminf(mn[i], fminf(fminf(v0, v1), fminf(v2, v3)));
            mx[i] = fmaxf(mx[i], fmaxf(fmaxf(v0, v1), fmaxf(v2, v3)));
        }
    }
    for (; e < deg; e++) {
        int s = g_srt[st + e];
        const float* row = H + s * F;
#pragma unroll
        for (int i = 0; i < FPT; i++) {
            float v = row[lane + 32 * i];
            sum[i] += v;
            ssq[i] += v * v;
            mn[i] = fminf(mn[i], v);
            mx[i] = fmaxf(mx[i], v);
        }
    }
    float inv = 1.f / (float)(deg > 1 ? deg : 1);
    float* out = g_agg + n * (4 * F);
#pragma unroll
    for (int i = 0; i < FPT; i++) {
        int f = lane + 32 * i;
        float mean = sum[i] * inv;
        float msq = ssq[i] * inv;
        float sd = sqrtf(fmaxf(msq - mean * mean, 0.f) + 1e-5f);
        float lmn = (deg > 0) ? mn[i] : 0.f;
        float lmx = (deg > 0) ? mx[i] : 0.f;
        out[f] = mean;
        out[F + f] = lmn;
        out[2 * F + f] = lmx;
        out[3 * F + f] = sd;
    }
}

// ---------------- fused PNA GEMM: R0 structure + f32x2 column-packed FMA ----
// block: 64 nodes x FO cols, 256 threads, BK=32. A-tiles built on the fly
// (k-major coalesced build, node-major padded SMEM layout).
template <int F, int FO, int CPT, bool RELU>
__global__ void __launch_bounds__(256) k_gemm(const float* __restrict__ H,
                                              const float* __restrict__ W,
                                              const float* __restrict__ B,
                                              float* __restrict__ OUT) {
    constexpr int K = 13 * F;
    constexpr int FOP = 16 * CPT;  // padded cols (multiple of 2)
    constexpr int F4 = 4 * F;
    constexpr int NP = CPT / 2;
    __shared__ float As[64 * 33];
    __shared__ float Ws[32 * FOP];
    int tid = threadIdx.x;
    int ct = tid >> 4;   // 0..15  col group
    int nt = tid & 15;   // 0..15  node group (4 nodes each)
    int n0 = blockIdx.x * 64;
    unsigned long long acc[4][NP];
#pragma unroll
    for (int i = 0; i < 4; i++)
#pragma unroll
        for (int j = 0; j < NP; j++) acc[i][j] = 0ull;

    for (int kt = 0; kt < K; kt += 32) {
        // load W tile (coalesced; zero-pad cols >= FO)
        for (int idx = tid; idx < 32 * FOP; idx += 256) {
            int kk = idx / FOP;
            int c = idx - kk * FOP;
            float v = 0.f;
            if (c < FO) v = W[(kt + kk) * FO + c];
            Ws[kk * FOP + c] = v;
        }
        // build A tile on the fly (coalesced along k)
        for (int idx = tid; idx < 2048; idx += 256) {
            int nl = idx >> 5;
            int kk = idx & 31;
            int n = n0 + nl;
            float v = 0.f;
            if (n < NN) {
                int k = kt + kk;
                if (k < F) {
                    v = H[(size_t)n * F + k];
                } else {
                    int j = k - F;
                    float sc;
                    int jj;
                    if (j < F4)          { sc = 1.f;     jj = j; }
                    else if (j < 2 * F4) { sc = g_s1[n]; jj = j - F4; }
                    else                 { sc = g_s2[n]; jj = j - 2 * F4; }
                    v = g_agg[(size_t)n * F4 + jj] * sc;
                }
            }
            As[nl * 33 + kk] = v;
        }
        __syncthreads();
#pragma unroll
        for (int kk = 0; kk < 32; kk++) {
            float a0 = As[(nt * 4 + 0) * 33 + kk];
            float a1 = As[(nt * 4 + 1) * 33 + kk];
            float a2 = As[(nt * 4 + 2) * 33 + kk];
            float a3 = As[(nt * 4 + 3) * 33 + kk];
            unsigned long long ap0 = pk2(a0, a0);
            unsigned long long ap1 = pk2(a1, a1);
            unsigned long long ap2 = pk2(a2, a2);
            unsigned long long ap3 = pk2(a3, a3);
            const float* Wk = Ws + kk * FOP + ct * CPT;
#pragma unroll
            for (int j = 0; j < NP; j++) {
                // float2 bit layout == f32x2 packing (lo=x, hi=y): load directly as b64
                unsigned long long wp = *(const unsigned long long*)&Wk[2 * j];
                fma2(acc[0][j], ap0, wp);
                fma2(acc[1][j], ap1, wp);
                fma2(acc[2][j], ap2, wp);
                fma2(acc[3][j], ap3, wp);
            }
        }
        __syncthreads();
    }
#pragma unroll
    for (int i = 0; i < 4; i++) {
        int n = n0 + nt * 4 + i;
        if (n < NN) {
#pragma unroll
            for (int j = 0; j < NP; j++) {
                float2 v = unpk(acc[i][j]);
                int c0 = ct * CPT + 2 * j;
                if (c0 < FO) {
                    float r = v.x + B[c0];
                    if (RELU) r = fmaxf(r, 0.f);
                    OUT[(size_t)n * FO + c0] = r;
                }
                if (c0 + 1 < FO) {
                    float r = v.y + B[c0 + 1];
                    if (RELU) r = fmaxf(r, 0.f);
                    OUT[(size_t)n * FO + c0 + 1] = r;
                }
            }
        }
    }
}

// ---------------- batchnorm ----------------
__global__ void k_bnzero() {
    int i = threadIdx.x;
    if (i < 128) { g_bnsum[i] = 0.f; g_bnssq[i] = 0.f; }
}

template <int C>
__global__ void k_bnstats(const float* __restrict__ h) {
    int c = threadIdx.x;
    if (c >= C) return;
    float s = 0.f, q = 0.f;
    for (int r = blockIdx.x; r < NN; r += gridDim.x) {
        float v = h[(size_t)r * C + c];
        s += v;
        q += v * v;
    }
    atomicAdd(&g_bnsum[c], s);
    atomicAdd(&g_bnssq[c], q);
}

template <int C>
__global__ void k_bnfin(const float* __restrict__ g, const float* __restrict__ be) {
    int c = threadIdx.x;
    if (c < C) {
        float mu = g_bnsum[c] / (float)NN;
        float var = g_bnssq[c] / (float)NN - mu * mu;
        float rs = rsqrtf(var + 1e-5f);
        float sc = g[c] * rs;
        g_scale[c] = sc;
        g_shift[c] = be[c] - mu * sc;
    }
}

template <int C, bool RELU>
__global__ void k_bnapply(float* __restrict__ h) {
    int i = blockIdx.x * 256 + threadIdx.x;
    if (i < NN * C) {
        int c = i % C;
        float v = h[i] * g_scale[c] + g_shift[c];
        if (RELU) v = fmaxf(v, 0.f);
        h[i] = v;
    }
}

// ---------------- pooling + head ----------------
__global__ void k_pool(const float* __restrict__ h, const int* __restrict__ batch) {
    int i = blockIdx.x * 256 + threadIdx.x;
    if (i < NN) {
        int g = batch[i];
        atomicAdd(&g_gcnt[g], 1);
        const float* row = h + (size_t)i * 20;
#pragma unroll
        for (int c = 0; c < 20; c++) {
            float v = row[c] * g_scale[c] + g_shift[c];
            atomicAdd(&g_zsum[g * 20 + c], v);
        }
    }
}

__global__ void k_final(const float* __restrict__ wl, const float* __restrict__ bl,
                        float* __restrict__ out, int out_size) {
    int g = threadIdx.x;
    if (g >= NGR) return;
    float inv = 1.f / fmaxf((float)g_gcnt[g], 1.f);
    float z[20];
#pragma unroll
    for (int c = 0; c < 20; c++) z[c] = g_zsum[g * 20 + c] * inv;
    float lo[11];
    float m = -3.4e38f;
#pragma unroll
    for (int o = 0; o < 11; o++) {
        float a = bl[o];
#pragma unroll
        for (int c = 0; c < 20; c++) a += z[c] * wl[c * 11 + o];
        lo[o] = a;
        m = fmaxf(m, a);
    }
    float ssum = 0.f;
#pragma unroll
    for (int o = 0; o < 11; o++) { lo[o] = expf(lo[o] - m); ssum += lo[o]; }
    float isum = 1.f / ssum;
#pragma unroll
    for (int o = 0; o < 11; o++) {
        int idx = g * 11 + o;
        if (idx < out_size) out[idx] = lo[o] * isum;
    }
#pragma unroll
    for (int c = 0; c < 20; c++) {
        int idx = NGR * 11 + g * 20 + c;
        if (idx < out_size) out[idx] = z[c];
    }
}

// ---------------- launcher ----------------
extern "C" void kernel_launch(void* const* d_in, const int* in_sizes, int n_in,
                              void* d_out, int out_size) {
    const float* x = (const float*)d_in[0];
    const int* ei = (const int*)d_in[1];
    const int* src = ei;
    const int* dst = ei + NE;
    const int* batch = (const int*)d_in[2];
    const float* w0 = (const float*)d_in[3];  const float* b0 = (const float*)d_in[4];
    const float* w1 = (const float*)d_in[5];  const float* b1 = (const float*)d_in[6];
    const float* w2 = (const float*)d_in[7];  const float* b2 = (const float*)d_in[8];
    const float* w3 = (const float*)d_in[9];  const float* b3 = (const float*)d_in[10];
    const float* g0 = (const float*)d_in[11]; const float* be0 = (const float*)d_in[12];
    const float* g1 = (const float*)d_in[13]; const float* be1 = (const float*)d_in[14];
    const float* g2 = (const float*)d_in[15]; const float* be2 = (const float*)d_in[16];
    const float* wl = (const float*)d_in[17]; const float* bl = (const float*)d_in[18];

    void* pA = 0; void* pB = 0;
    cudaGetSymbolAddress(&pA, g_hA);
    cudaGetSymbolAddress(&pB, g_hB);
    float* hA = (float*)pA;
    float* hB = (float*)pB;

    const int GB_E = (NE + 255) / 256;     // 12500
    const int GB_N = (NN + 255) / 256;     // 391
    const int GB_G = (NN + 63) / 64;       // 1563

    k_zero<<<GB_N, 256>>>();
    k_count<<<GB_E, 256>>>(dst);
    k_scan1<<<GB_N, 256>>>();
    k_scan2<<<1, 512>>>();
    k_scan3<<<GB_N, 256>>>();
    k_scatter<<<GB_E, 256>>>(src, dst);
    k_prep<<<GB_N, 256>>>();

    // layer 0: 64 -> 96, BN + relu
    k_agg<64><<<(NN * 32 + 255) / 256, 256>>>(x);
    k_gemm<64, 96, 6, false><<<GB_G, 256>>>(x, w0, b0, hA);
    k_bnzero<<<1, 128>>>();
    k_bnstats<96><<<512, 96>>>(hA);
    k_bnfin<96><<<1, 96>>>(g0, be0);
    k_bnapply<96, true><<<(NN * 96 + 255) / 256, 256>>>(hA);

    // layer 1: 96 -> 64, BN + relu
    k_agg<96><<<(NN * 32 + 255) / 256, 256>>>(hA);
    k_gemm<96, 64, 4, false><<<GB_G, 256>>>(hA, w1, b1, hB);
    k_bnzero<<<1, 128>>>();
    k_bnstats<64><<<512, 64>>>(hB);
    k_bnfin<64><<<1, 64>>>(g1, be1);
    k_bnapply<64, true><<<(NN * 64 + 255) / 256, 256>>>(hB);

    // layer 2: 64 -> 32, relu fused in epilogue
    k_agg<64><<<(NN * 32 + 255) / 256, 256>>>(hB);
    k_gemm<64, 32, 2, true><<<GB_G, 256>>>(hB, w2, b2, hA);

    // layer 3: 32 -> 20, BN affine fused into pooling
    k_agg<32><<<(NN * 32 + 255) / 256, 256>>>(hA);
    k_gemm<32, 20, 2, false><<<GB_G, 256>>>(hA, w3, b3, hB);
    k_bnzero<<<1, 128>>>();
    k_bnstats<20><<<512, 32>>>(hB);
    k_bnfin<20><<<1, 32>>>(g2, be2);

    k_pool<<<GB_N, 256>>>(hB, batch);
    k_final<<<1, 64>>>(wl, bl, (float*)d_out, out_size);
}

// round 6
// speedup vs baseline: 1.6817x; 1.2712x over previous
#include <cuda_runtime.h>
#include <cuda_bf16.h>
#include <math.h>
#include <stdint.h>

#define NN 100000
#define NE 3200000
#define NGR 64
typedef unsigned short u16;
static __device__ __constant__ float AVG_LOG_C = 3.4965076f; // log(33.0)

// ---------------- scratch (device globals; no allocations) ----------------
__device__ int   g_cnt[NN];
__device__ int   g_fill[NN];
__device__ int   g_rowstart[NN];
__device__ int   g_bsum[512];
__device__ int   g_boff[512];
__device__ int   g_srt[NE];
__device__ float g_s1[NN];
__device__ float g_s2[NN];
__device__ float g_hA[NN * 96];
__device__ float g_hB[NN * 96];
__device__ float g_agg[NN * 384];
__device__ __align__(16) u16 g_Whi[81920];
__device__ __align__(16) u16 g_Wlo[81920];
__device__ float g_bnsum[128];
__device__ float g_bnssq[128];
__device__ float g_scale[128];
__device__ float g_shift[128];
__device__ float g_zsum[NGR * 20];
__device__ int   g_gcnt[NGR];

// ---------------- mma helpers (sm_80+ portable) ----------------
__device__ __forceinline__ uint32_t smem_u32(const void* p) {
    uint32_t a;
    asm("{ .reg .u64 t; cvta.to.shared.u64 t, %1; cvt.u32.u64 %0, t; }" : "=r"(a) : "l"(p));
    return a;
}
__device__ __forceinline__ void ldm_x4(uint32_t* r, uint32_t addr) {
    asm volatile("ldmatrix.sync.aligned.m8n8.x4.shared.b16 {%0,%1,%2,%3}, [%4];"
        : "=r"(r[0]), "=r"(r[1]), "=r"(r[2]), "=r"(r[3]) : "r"(addr));
}
__device__ __forceinline__ void ldm_x4t(uint32_t* r, uint32_t addr) {
    asm volatile("ldmatrix.sync.aligned.m8n8.x4.trans.shared.b16 {%0,%1,%2,%3}, [%4];"
        : "=r"(r[0]), "=r"(r[1]), "=r"(r[2]), "=r"(r[3]) : "r"(addr));
}
__device__ __forceinline__ void mma_bf16(float* d, const uint32_t* a, const uint32_t* b) {
    asm volatile(
        "mma.sync.aligned.m16n8k16.row.col.f32.bf16.bf16.f32 "
        "{%0,%1,%2,%3}, {%4,%5,%6,%7}, {%8,%9}, {%0,%1,%2,%3};"
        : "+f"(d[0]), "+f"(d[1]), "+f"(d[2]), "+f"(d[3])
        : "r"(a[0]), "r"(a[1]), "r"(a[2]), "r"(a[3]), "r"(b[0]), "r"(b[1]));
}

// ---------------- graph preprocessing ----------------
__global__ void k_zero() {
    int i = blockIdx.x * 256 + threadIdx.x;
    if (i < NN) { g_cnt[i] = 0; g_fill[i] = 0; }
    if (i < NGR * 20) g_zsum[i] = 0.f;
    if (i < NGR) g_gcnt[i] = 0;
}

__global__ void k_count(const int* __restrict__ dst) {
    int i = blockIdx.x * 256 + threadIdx.x;
    if (i < NE) atomicAdd(&g_cnt[dst[i]], 1);
}

__global__ void k_scan1() {
    __shared__ int s[256];
    int tid = threadIdx.x;
    int i = blockIdx.x * 256 + tid;
    s[tid] = (i < NN) ? g_cnt[i] : 0;
    __syncthreads();
    for (int off = 128; off > 0; off >>= 1) {
        if (tid < off) s[tid] += s[tid + off];
        __syncthreads();
    }
    if (tid == 0) g_bsum[blockIdx.x] = s[0];
}

__global__ void k_scan2() {
    __shared__ int s[512];
    int tid = threadIdx.x;
    int v = (tid < 391) ? g_bsum[tid] : 0;
    s[tid] = v;
    __syncthreads();
    for (int off = 1; off < 512; off <<= 1) {
        int t = (tid >= off) ? s[tid - off] : 0;
        __syncthreads();
        s[tid] += t;
        __syncthreads();
    }
    g_boff[tid] = s[tid] - v;
}

__global__ void k_scan3() {
    __shared__ int s[256];
    int tid = threadIdx.x;
    int i = blockIdx.x * 256 + tid;
    int v = (i < NN) ? g_cnt[i] : 0;
    s[tid] = v;
    __syncthreads();
    for (int off = 1; off < 256; off <<= 1) {
        int t = (tid >= off) ? s[tid - off] : 0;
        __syncthreads();
        s[tid] += t;
        __syncthreads();
    }
    if (i < NN) g_rowstart[i] = g_boff[blockIdx.x] + s[tid] - v;
}

__global__ void k_scatter(const int* __restrict__ src, const int* __restrict__ dst) {
    int i = blockIdx.x * 256 + threadIdx.x;
    if (i < NE) {
        int d = dst[i];
        int p = g_rowstart[d] + atomicAdd(&g_fill[d], 1);
        g_srt[p] = src[i];
    }
}

__global__ void k_prep() {
    int i = blockIdx.x * 256 + threadIdx.x;
    if (i < NN) {
        int deg = g_cnt[i];
        float degc = (float)(deg > 1 ? deg : 1);
        float logd = logf(degc + 1.f);
        g_s1[i] = logd / AVG_LOG_C;
        g_s2[i] = AVG_LOG_C / logd;
    }
}

// ---------------- per-node segmented aggregation (warp per node) ----------------
template <int F>
__global__ void __launch_bounds__(256) k_agg(const float* __restrict__ H) {
    constexpr int FPT = F / 32;
    int wid = (blockIdx.x * 256 + threadIdx.x) >> 5;
    int lane = threadIdx.x & 31;
    if (wid >= NN) return;
    int n = wid;
    int deg = g_cnt[n];
    int st = g_rowstart[n];
    float sum[FPT], ssq[FPT], mn[FPT], mx[FPT];
#pragma unroll
    for (int i = 0; i < FPT; i++) { sum[i] = 0.f; ssq[i] = 0.f; mn[i] = 3.4e38f; mx[i] = -3.4e38f; }
    int e = 0;
    for (; e + 4 <= deg; e += 4) {
        int s0 = g_srt[st + e + 0];
        int s1 = g_srt[st + e + 1];
        int s2 = g_srt[st + e + 2];
        int s3 = g_srt[st + e + 3];
        const float* r0 = H + (size_t)s0 * F;
        const float* r1 = H + (size_t)s1 * F;
        const float* r2 = H + (size_t)s2 * F;
        const float* r3 = H + (size_t)s3 * F;
#pragma unroll
        for (int i = 0; i < FPT; i++) {
            int f = lane + 32 * i;
            float v0 = r0[f], v1 = r1[f], v2 = r2[f], v3 = r3[f];
            sum[i] += v0 + v1 + v2 + v3;
            ssq[i] += v0 * v0 + v1 * v1 + v2 * v2 + v3 * v3;
            mn[i] = fminf(mn[i], fminf(fminf(v0, v1), fminf(v2, v3)));
            mx[i] = fmaxf(mx[i], fmaxf(fmaxf(v0, v1), fmaxf(v2, v3)));
        }
    }
    for (; e < deg; e++) {
        int s = g_srt[st + e];
        const float* row = H + (size_t)s * F;
#pragma unroll
        for (int i = 0; i < FPT; i++) {
            float v = row[lane + 32 * i];
            sum[i] += v;
            ssq[i] += v * v;
            mn[i] = fminf(mn[i], v);
            mx[i] = fmaxf(mx[i], v);
        }
    }
    float inv = 1.f / (float)(deg > 1 ? deg : 1);
    float* out = g_agg + (size_t)n * (4 * F);
#pragma unroll
    for (int i = 0; i < FPT; i++) {
        int f = lane + 32 * i;
        float mean = sum[i] * inv;
        float msq = ssq[i] * inv;
        float sd = sqrtf(fmaxf(msq - mean * mean, 0.f) + 1e-5f);
        float lmn = (deg > 0) ? mn[i] : 0.f;
        float lmx = (deg > 0) ? mx[i] : 0.f;
        out[f] = mean;
        out[F + f] = lmn;
        out[2 * F + f] = lmx;
        out[3 * F + f] = sd;
    }
}

// ---------------- W pre-conversion: fp32 -> bf16 hi/lo, [K13][FOP_] ----------
template <int K13, int FO, int FOP_>
__global__ void k_wconv(const float* __restrict__ W) {
    int i = blockIdx.x * 256 + threadIdx.x;
    if (i >= K13 * FOP_) return;
    int k = i / FOP_;
    int c = i - k * FOP_;
    float v = (c < FO) ? W[(size_t)k * FO + c] : 0.f;
    uint32_t bits = __float_as_uint(v);
    u16 hi = (u16)(bits >> 16);                               // truncation split (exact)
    float lo = v - __uint_as_float(bits & 0xFFFF0000u);
    g_Whi[i] = hi;
    g_Wlo[i] = (u16)(__float_as_uint(__float2bfloat16(lo) == __float2bfloat16(lo) ? 0.f : 0.f), 0); // placeholder (overwritten below)
    __nv_bfloat16 lb = __float2bfloat16(lo);
    g_Wlo[i] = *(u16*)&lb;
}

// ---------------- PNA GEMM via mma.sync bf16 (3-term hi/lo split) ------------
// A[n, k] = [x | agg | s1*agg | s2*agg] built on the fly into bf16 hi/lo SMEM.
// Block: 128 nodes x FO cols; warps 4(M) x 2(N); warp tile 32 x NT*8.
template <int F, int FO, int FOP_, int NT, int WSTR, bool RELU>
__global__ void __launch_bounds__(256) k_mma(const float* __restrict__ H,
                                             const float* __restrict__ Bias,
                                             float* __restrict__ OUT) {
    constexpr int K13 = 13 * F;
    constexpr int KT = K13 / 32;
    constexpr int ASTR = 40;               // 32 + 8 pad: conflict-free ldmatrix
    constexpr int F4 = 4 * F;
    constexpr int WCOLS = NT * 16;         // cols touched by ldmatrix (2 warps in N)
    __shared__ __align__(16) u16 sAhi[128 * ASTR];
    __shared__ __align__(16) u16 sAlo[128 * ASTR];
    __shared__ __align__(16) u16 sWhi[32 * WSTR];
    __shared__ __align__(16) u16 sWlo[32 * WSTR];
    __shared__ float sS1[128], sS2[128];

    int tid = threadIdx.x;
    int lane = tid & 31;
    int wid = tid >> 5;
    int warpM = wid & 3;
    int warpN = wid >> 2;
    int n0 = blockIdx.x * 128;

    if (tid < 128) {
        int n = n0 + tid;
        sS1[tid] = (n < NN) ? g_s1[n] : 0.f;
        sS2[tid] = (n < NN) ? g_s2[n] : 0.f;
    }
    if (FOP_ < WCOLS) {   // zero pad cols once (never rewritten)
        for (int i = tid; i < 32 * (WCOLS - FOP_); i += 256) {
            int kr = i / (WCOLS - FOP_);
            int c = FOP_ + i % (WCOLS - FOP_);
            sWhi[kr * WSTR + c] = 0;
            sWlo[kr * WSTR + c] = 0;
        }
    }
    __syncthreads();

    uint32_t aAhi = smem_u32(sAhi), aAlo = smem_u32(sAlo);
    uint32_t aWhi = smem_u32(sWhi), aWlo = smem_u32(sWlo);

    float acc[2][NT][4];
#pragma unroll
    for (int m = 0; m < 2; m++)
#pragma unroll
        for (int n = 0; n < NT; n++)
#pragma unroll
            for (int j = 0; j < 4; j++) acc[m][n][j] = 0.f;

    // per-lane ldmatrix offsets (canonical x4 mapping)
    int q = lane >> 3, r = lane & 7;
    uint32_t aoff = (uint32_t)((warpM * 32 + (q & 1) * 8 + r) * ASTR + (q >> 1) * 8) * 2;
    uint32_t boff = (uint32_t)(((q & 1) * 8 + r) * WSTR + warpN * NT * 8 + (q >> 1) * 8) * 2;

    for (int t = 0; t < KT; t++) {
        int kb = t * 32;
        // ---- build A tile (hi/lo), coalesced along k ----
#pragma unroll
        for (int p = 0; p < 8; p++) {
            int idx = tid + p * 256;
            int row = idx >> 4;
            int kp = idx & 15;
            int n = n0 + row;
            int k = kb + 2 * kp;
            float2 v = make_float2(0.f, 0.f);
            if (n < NN) {
                if (k < F) {
                    v = *(const float2*)&H[(size_t)n * F + k];
                } else {
                    int j = k - F;
                    float sc;
                    int jj;
                    if (j < F4)          { sc = 1.f;      jj = j; }
                    else if (j < 2 * F4) { sc = sS1[row]; jj = j - F4; }
                    else                 { sc = sS2[row]; jj = j - 2 * F4; }
                    float2 a = *(const float2*)&g_agg[(size_t)n * F4 + jj];
                    v.x = a.x * sc;
                    v.y = a.y * sc;
                }
            }
            uint32_t xi = __float_as_uint(v.x), yi = __float_as_uint(v.y);
            uint32_t hip = __byte_perm(xi, yi, 0x7632);   // {hi16(x), hi16(y)}
            float lx = v.x - __uint_as_float(xi & 0xFFFF0000u);
            float ly = v.y - __uint_as_float(yi & 0xFFFF0000u);
            __nv_bfloat162 lop = __floats2bfloat162_rn(lx, ly);
            *(uint32_t*)&sAhi[row * ASTR + 2 * kp] = hip;
            *(uint32_t*)&sAlo[row * ASTR + 2 * kp] = *(uint32_t*)&lop;
        }
        // ---- copy W tile (pre-converted bf16) ----
        {
            constexpr int NU4 = 32 * FOP_ / 8;
            for (int i = tid; i < NU4; i += 256) {
                int kr = i / (FOP_ / 8);
                int ch = i - kr * (FOP_ / 8);
                uint4 vh = *(const uint4*)&g_Whi[(size_t)(kb + kr) * FOP_ + ch * 8];
                uint4 vl = *(const uint4*)&g_Wlo[(size_t)(kb + kr) * FOP_ + ch * 8];
                *(uint4*)&sWhi[kr * WSTR + ch * 8] = vh;
                *(uint4*)&sWlo[kr * WSTR + ch * 8] = vl;
            }
        }
        __syncthreads();
        // ---- compute: 2 k16 steps ----
#pragma unroll
        for (int ks = 0; ks < 32; ks += 16) {
            uint32_t ah[2][4], al[2][4];
            ldm_x4(ah[0], aAhi + aoff + 2 * ks);
            ldm_x4(ah[1], aAhi + aoff + 2 * ks + 16 * ASTR * 2);
            ldm_x4(al[0], aAlo + aoff + 2 * ks);
            ldm_x4(al[1], aAlo + aoff + 2 * ks + 16 * ASTR * 2);
            uint32_t bh[NT][2], bl[NT][2];
#pragma unroll
            for (int p2 = 0; p2 < NT / 2; p2++) {
                uint32_t r4[4];
                ldm_x4t(r4, aWhi + boff + 2 * (ks * WSTR) + p2 * 32);
                bh[2 * p2][0] = r4[0]; bh[2 * p2][1] = r4[1];
                bh[2 * p2 + 1][0] = r4[2]; bh[2 * p2 + 1][1] = r4[3];
                ldm_x4t(r4, aWlo + boff + 2 * (ks * WSTR) + p2 * 32);
                bl[2 * p2][0] = r4[0]; bl[2 * p2][1] = r4[1];
                bl[2 * p2 + 1][0] = r4[2]; bl[2 * p2 + 1][1] = r4[3];
            }
#pragma unroll
            for (int m = 0; m < 2; m++)
#pragma unroll
                for (int nt2 = 0; nt2 < NT; nt2++) {
                    mma_bf16(acc[m][nt2], ah[m], bh[nt2]);
                    mma_bf16(acc[m][nt2], al[m], bh[nt2]);
                    mma_bf16(acc[m][nt2], ah[m], bl[nt2]);
                }
        }
        __syncthreads();
    }
    // ---- epilogue ----
    int gi = lane >> 2, ti = lane & 3;
#pragma unroll
    for (int m = 0; m < 2; m++) {
        int row0 = n0 + warpM * 32 + m * 16 + gi;
#pragma unroll
        for (int nt2 = 0; nt2 < NT; nt2++) {
            int col = warpN * NT * 8 + nt2 * 8 + ti * 2;
            if (col < FO) {   // FO even -> col+1 < FO too
                float b0v = Bias[col], b1v = Bias[col + 1];
                if (row0 < NN) {
                    float r0v = acc[m][nt2][0] + b0v;
                    float r1v = acc[m][nt2][1] + b1v;
                    if (RELU) { r0v = fmaxf(r0v, 0.f); r1v = fmaxf(r1v, 0.f); }
                    OUT[(size_t)row0 * FO + col] = r0v;
                    OUT[(size_t)row0 * FO + col + 1] = r1v;
                }
                if (row0 + 8 < NN) {
                    float r2v = acc[m][nt2][2] + b0v;
                    float r3v = acc[m][nt2][3] + b1v;
                    if (RELU) { r2v = fmaxf(r2v, 0.f); r3v = fmaxf(r3v, 0.f); }
                    OUT[(size_t)(row0 + 8) * FO + col] = r2v;
                    OUT[(size_t)(row0 + 8) * FO + col + 1] = r3v;
                }
            }
        }
    }
}

// ---------------- batchnorm ----------------
__global__ void k_bnzero() {
    int i = threadIdx.x;
    if (i < 128) { g_bnsum[i] = 0.f; g_bnssq[i] = 0.f; }
}

template <int C>
__global__ void k_bnstats(const float* __restrict__ h) {
    int c = threadIdx.x;
    if (c >= C) return;
    float s = 0.f, q = 0.f;
    for (int r = blockIdx.x; r < NN; r += gridDim.x) {
        float v = h[(size_t)r * C + c];
        s += v;
        q += v * v;
    }
    atomicAdd(&g_bnsum[c], s);
    atomicAdd(&g_bnssq[c], q);
}

template <int C>
__global__ void k_bnfin(const float* __restrict__ g, const float* __restrict__ be) {
    int c = threadIdx.x;
    if (c < C) {
        float mu = g_bnsum[c] / (float)NN;
        float var = g_bnssq[c] / (float)NN - mu * mu;
        float rs = rsqrtf(var + 1e-5f);
        float sc = g[c] * rs;
        g_scale[c] = sc;
        g_shift[c] = be[c] - mu * sc;
    }
}

template <int C, bool RELU>
__global__ void k_bnapply(float* __restrict__ h) {
    int i = blockIdx.x * 256 + threadIdx.x;
    if (i < NN * C) {
        int c = i % C;
        float v = h[i] * g_scale[c] + g_shift[c];
        if (RELU) v = fmaxf(v, 0.f);
        h[i] = v;
    }
}

// ---------------- pooling + head ----------------
__global__ void k_pool(const float* __restrict__ h, const int* __restrict__ batch) {
    int i = blockIdx.x * 256 + threadIdx.x;
    if (i < NN) {
        int g = batch[i];
        atomicAdd(&g_gcnt[g], 1);
        const float* row = h + (size_t)i * 20;
#pragma unroll
        for (int c = 0; c < 20; c++) {
            float v = row[c] * g_scale[c] + g_shift[c];
            atomicAdd(&g_zsum[g * 20 + c], v);
        }
    }
}

__global__ void k_final(const float* __restrict__ wl, const float* __restrict__ bl,
                        float* __restrict__ out, int out_size) {
    int g = threadIdx.x;
    if (g >= NGR) return;
    float inv = 1.f / fmaxf((float)g_gcnt[g], 1.f);
    float z[20];
#pragma unroll
    for (int c = 0; c < 20; c++) z[c] = g_zsum[g * 20 + c] * inv;
    float lo[11];
    float m = -3.4e38f;
#pragma unroll
    for (int o = 0; o < 11; o++) {
        float a = bl[o];
#pragma unroll
        for (int c = 0; c < 20; c++) a += z[c] * wl[c * 11 + o];
        lo[o] = a;
        m = fmaxf(m, a);
    }
    float ssum = 0.f;
#pragma unroll
    for (int o = 0; o < 11; o++) { lo[o] = expf(lo[o] - m); ssum += lo[o]; }
    float isum = 1.f / ssum;
#pragma unroll
    for (int o = 0; o < 11; o++) {
        int idx = g * 11 + o;
        if (idx < out_size) out[idx] = lo[o] * isum;
    }
#pragma unroll
    for (int c = 0; c < 20; c++) {
        int idx = NGR * 11 + g * 20 + c;
        if (idx < out_size) out[idx] = z[c];
    }
}

// ---------------- launcher ----------------
extern "C" void kernel_launch(void* const* d_in, const int* in_sizes, int n_in,
                              void* d_out, int out_size) {
    const float* x = (const float*)d_in[0];
    const int* ei = (const int*)d_in[1];
    const int* src = ei;
    const int* dst = ei + NE;
    const int* batch = (const int*)d_in[2];
    const float* w0 = (const float*)d_in[3];  const float* b0 = (const float*)d_in[4];
    const float* w1 = (const float*)d_in[5];  const float* b1 = (const float*)d_in[6];
    const float* w2 = (const float*)d_in[7];  const float* b2 = (const float*)d_in[8];
    const float* w3 = (const float*)d_in[9];  const float* b3 = (const float*)d_in[10];
    const float* g0 = (const float*)d_in[11]; const float* be0 = (const float*)d_in[12];
    const float* g1 = (const float*)d_in[13]; const float* be1 = (const float*)d_in[14];
    const float* g2 = (const float*)d_in[15]; const float* be2 = (const float*)d_in[16];
    const float* wl = (const float*)d_in[17]; const float* bl = (const float*)d_in[18];

    void* pA = 0; void* pB = 0;
    cudaGetSymbolAddress(&pA, g_hA);
    cudaGetSymbolAddress(&pB, g_hB);
    float* hA = (float*)pA;
    float* hB = (float*)pB;

    const int GB_E = (NE + 255) / 256;
    const int GB_N = (NN + 255) / 256;
    const int GB_M = (NN + 127) / 128;   // 782 blocks

    k_zero<<<GB_N, 256>>>();
    k_count<<<GB_E, 256>>>(dst);
    k_scan1<<<GB_N, 256>>>();
    k_scan2<<<1, 512>>>();
    k_scan3<<<GB_N, 256>>>();
    k_scatter<<<GB_E, 256>>>(src, dst);
    k_prep<<<GB_N, 256>>>();

    // layer 0: 64 -> 96, BN + relu
    k_agg<64><<<(NN * 32 + 255) / 256, 256>>>(x);
    k_wconv<832, 96, 96><<<(832 * 96 + 255) / 256, 256>>>(w0);
    k_mma<64, 96, 96, 6, 104, false><<<GB_M, 256>>>(x, b0, hA);
    k_bnzero<<<1, 128>>>();
    k_bnstats<96><<<512, 96>>>(hA);
    k_bnfin<96><<<1, 96>>>(g0, be0);
    k_bnapply<96, true><<<(NN * 96 + 255) / 256, 256>>>(hA);

    // layer 1: 96 -> 64, BN + relu
    k_agg<96><<<(NN * 32 + 255) / 256, 256>>>(hA);
    k_wconv<1248, 64, 64><<<(1248 * 64 + 255) / 256, 256>>>(w1);
    k_mma<96, 64, 64, 4, 72, false><<<GB_M, 256>>>(hA, b1, hB);
    k_bnzero<<<1, 128>>>();
    k_bnstats<64><<<512, 64>>>(hB);
    k_bnfin<64><<<1, 64>>>(g1, be1);
    k_bnapply<64, true><<<(NN * 64 + 255) / 256, 256>>>(hB);

    // layer 2: 64 -> 32, relu fused in epilogue
    k_agg<64><<<(NN * 32 + 255) / 256, 256>>>(hB);
    k_wconv<832, 32, 32><<<(832 * 32 + 255) / 256, 256>>>(w2);
    k_mma<64, 32, 32, 2, 40, true><<<GB_M, 256>>>(hB, b2, hA);

    // layer 3: 32 -> 20, BN affine fused into pooling
    k_agg<32><<<(NN * 32 + 255) / 256, 256>>>(hA);
    k_wconv<416, 20, 24><<<(416 * 24 + 255) / 256, 256>>>(w3);
    k_mma<32, 20, 24, 2, 40, false><<<GB_M, 256>>>(hA, b3, hB);
    k_bnzero<<<1, 128>>>();
    k_bnstats<20><<<512, 32>>>(hB);
    k_bnfin<20><<<1, 32>>>(g2, be2);

    k_pool<<<GB_N, 256>>>(hB, batch);
    k_final<<<1, 64>>>(wl, bl, (float*)d_out, out_size);
}

// round 7
// speedup vs baseline: 1.7889x; 1.0638x over previous
#include <cuda_runtime.h>
#include <cuda_bf16.h>
#include <math.h>
#include <stdint.h>

#define NN 100000
#define NE 3200000
#define NGR 64
typedef unsigned short u16;
static __device__ __constant__ float AVG_LOG_C = 3.4965076f; // log(33.0)

// ---------------- scratch (device globals; no allocations) ----------------
__device__ int   g_cnt[NN];
__device__ int   g_fill[NN];
__device__ int   g_rowstart[NN];
__device__ int   g_bsum[512];
__device__ int   g_boff[512];
__device__ int   g_srt[NE];
__device__ float g_s1[NN];
__device__ float g_s2[NN];
__device__ float g_hA[NN * 96];
__device__ float g_hB[NN * 96];
__device__ float g_agg[NN * 384];
__device__ __align__(16) u16 g_Whi[81920];
__device__ __align__(16) u16 g_Wlo[81920];
__device__ float g_bnsum[128];
__device__ float g_bnssq[128];
__device__ float g_scale[128];
__device__ float g_shift[128];
__device__ float g_zsum[NGR * 20];
__device__ int   g_gcnt[NGR];

// ---------------- helpers (sm_80+ portable) ----------------
__device__ __forceinline__ uint32_t smem_u32(const void* p) {
    uint32_t a;
    asm("{ .reg .u64 t; cvta.to.shared.u64 t, %1; cvt.u32.u64 %0, t; }" : "=r"(a) : "l"(p));
    return a;
}
__device__ __forceinline__ void ldm_x4(uint32_t* r, uint32_t addr) {
    asm volatile("ldmatrix.sync.aligned.m8n8.x4.shared.b16 {%0,%1,%2,%3}, [%4];"
        : "=r"(r[0]), "=r"(r[1]), "=r"(r[2]), "=r"(r[3]) : "r"(addr));
}
__device__ __forceinline__ void ldm_x4t(uint32_t* r, uint32_t addr) {
    asm volatile("ldmatrix.sync.aligned.m8n8.x4.trans.shared.b16 {%0,%1,%2,%3}, [%4];"
        : "=r"(r[0]), "=r"(r[1]), "=r"(r[2]), "=r"(r[3]) : "r"(addr));
}
__device__ __forceinline__ void mma_bf16(float* d, const uint32_t* a, const uint32_t* b) {
    asm volatile(
        "mma.sync.aligned.m16n8k16.row.col.f32.bf16.bf16.f32 "
        "{%0,%1,%2,%3}, {%4,%5,%6,%7}, {%8,%9}, {%0,%1,%2,%3};"
        : "+f"(d[0]), "+f"(d[1]), "+f"(d[2]), "+f"(d[3])
        : "r"(a[0]), "r"(a[1]), "r"(a[2]), "r"(a[3]), "r"(b[0]), "r"(b[1]));
}
__device__ __forceinline__ void cpa16(uint32_t dst, const void* src) {
    asm volatile("cp.async.cg.shared.global [%0], [%1], 16;" :: "r"(dst), "l"(src));
}
#define CPA_COMMIT() asm volatile("cp.async.commit_group;" ::: "memory")
#define CPA_WAIT0()  asm volatile("cp.async.wait_group 0;" ::: "memory")

// ---------------- graph preprocessing ----------------
__global__ void k_zero() {
    int i = blockIdx.x * 256 + threadIdx.x;
    if (i < NN) g_cnt[i] = 0;
    if (i < NGR * 20) g_zsum[i] = 0.f;
    if (i < NGR) g_gcnt[i] = 0;
}

__global__ void k_count(const int* __restrict__ dst) {
    int i = blockIdx.x * 256 + threadIdx.x;
    if (i < NE) atomicAdd(&g_cnt[dst[i]], 1);
}

__global__ void k_scan1() {
    __shared__ int s[256];
    int tid = threadIdx.x;
    int i = blockIdx.x * 256 + tid;
    s[tid] = (i < NN) ? g_cnt[i] : 0;
    __syncthreads();
    for (int off = 128; off > 0; off >>= 1) {
        if (tid < off) s[tid] += s[tid + off];
        __syncthreads();
    }
    if (tid == 0) g_bsum[blockIdx.x] = s[0];
}

__global__ void k_scan2() {
    __shared__ int s[512];
    int tid = threadIdx.x;
    int v = (tid < 391) ? g_bsum[tid] : 0;
    s[tid] = v;
    __syncthreads();
    for (int off = 1; off < 512; off <<= 1) {
        int t = (tid >= off) ? s[tid - off] : 0;
        __syncthreads();
        s[tid] += t;
        __syncthreads();
    }
    g_boff[tid] = s[tid] - v;
}

// scan3 + prep fused: rowstart, fill=rowstart, degree scalers
__global__ void k_scan3() {
    __shared__ int s[256];
    int tid = threadIdx.x;
    int i = blockIdx.x * 256 + tid;
    int v = (i < NN) ? g_cnt[i] : 0;
    s[tid] = v;
    __syncthreads();
    for (int off = 1; off < 256; off <<= 1) {
        int t = (tid >= off) ? s[tid - off] : 0;
        __syncthreads();
        s[tid] += t;
        __syncthreads();
    }
    if (i < NN) {
        int rs = g_boff[blockIdx.x] + s[tid] - v;
        g_rowstart[i] = rs;
        g_fill[i] = rs;
        int deg = v;
        float degc = (float)(deg > 1 ? deg : 1);
        float logd = logf(degc + 1.f);
        g_s1[i] = logd / AVG_LOG_C;
        g_s2[i] = AVG_LOG_C / logd;
    }
}

__global__ void k_scatter(const int* __restrict__ src, const int* __restrict__ dst) {
    int i = blockIdx.x * 256 + threadIdx.x;
    if (i < NE) {
        int d = dst[i];
        int p = atomicAdd(&g_fill[d], 1);
        g_srt[p] = src[i];
    }
}

// ---------------- per-node segmented aggregation (warp per node) ----------------
template <int F>
__global__ void __launch_bounds__(256) k_agg(const float* __restrict__ H) {
    constexpr int FPT = F / 32;
    int wid = (blockIdx.x * 256 + threadIdx.x) >> 5;
    int lane = threadIdx.x & 31;
    if (wid >= NN) return;
    int n = wid;
    int deg = g_cnt[n];
    int st = g_rowstart[n];
    float sum[FPT], ssq[FPT], mn[FPT], mx[FPT];
#pragma unroll
    for (int i = 0; i < FPT; i++) { sum[i] = 0.f; ssq[i] = 0.f; mn[i] = 3.4e38f; mx[i] = -3.4e38f; }
    int e = 0;
    // 8-edge unrolled: high MLP against L2 latency
    for (; e + 8 <= deg; e += 8) {
        int sidx[8];
#pragma unroll
        for (int u = 0; u < 8; u++) sidx[u] = g_srt[st + e + u];
#pragma unroll
        for (int i = 0; i < FPT; i++) {
            int f = lane + 32 * i;
            float v[8];
#pragma unroll
            for (int u = 0; u < 8; u++) v[u] = H[(size_t)sidx[u] * F + f];
#pragma unroll
            for (int u = 0; u < 8; u++) {
                sum[i] += v[u];
                ssq[i] = fmaf(v[u], v[u], ssq[i]);
                mn[i] = fminf(mn[i], v[u]);
                mx[i] = fmaxf(mx[i], v[u]);
            }
        }
    }
    for (; e + 4 <= deg; e += 4) {
        int s0 = g_srt[st + e + 0];
        int s1 = g_srt[st + e + 1];
        int s2 = g_srt[st + e + 2];
        int s3 = g_srt[st + e + 3];
#pragma unroll
        for (int i = 0; i < FPT; i++) {
            int f = lane + 32 * i;
            float v0 = H[(size_t)s0 * F + f], v1 = H[(size_t)s1 * F + f];
            float v2 = H[(size_t)s2 * F + f], v3 = H[(size_t)s3 * F + f];
            sum[i] += v0 + v1 + v2 + v3;
            ssq[i] += v0 * v0 + v1 * v1 + v2 * v2 + v3 * v3;
            mn[i] = fminf(mn[i], fminf(fminf(v0, v1), fminf(v2, v3)));
            mx[i] = fmaxf(mx[i], fmaxf(fmaxf(v0, v1), fmaxf(v2, v3)));
        }
    }
    for (; e < deg; e++) {
        int s = g_srt[st + e];
#pragma unroll
        for (int i = 0; i < FPT; i++) {
            float v = H[(size_t)s * F + lane + 32 * i];
            sum[i] += v;
            ssq[i] += v * v;
            mn[i] = fminf(mn[i], v);
            mx[i] = fmaxf(mx[i], v);
        }
    }
    float inv = 1.f / (float)(deg > 1 ? deg : 1);
    float* out = g_agg + (size_t)n * (4 * F);
#pragma unroll
    for (int i = 0; i < FPT; i++) {
        int f = lane + 32 * i;
        float mean = sum[i] * inv;
        float msq = ssq[i] * inv;
        float sd = sqrtf(fmaxf(msq - mean * mean, 0.f) + 1e-5f);
        float lmn = (deg > 0) ? mn[i] : 0.f;
        float lmx = (deg > 0) ? mx[i] : 0.f;
        out[f] = mean;
        out[F + f] = lmn;
        out[2 * F + f] = lmx;
        out[3 * F + f] = sd;
    }
}

// ---------------- W pre-conversion: fp32 -> bf16 hi/lo, [K13][FOP_] ----------
template <int K13, int FO, int FOP_>
__global__ void k_wconv(const float* __restrict__ W) {
    int i = blockIdx.x * 256 + threadIdx.x;
    if (i >= K13 * FOP_) return;
    int k = i / FOP_;
    int c = i - k * FOP_;
    float v = (c < FO) ? W[(size_t)k * FO + c] : 0.f;
    uint32_t bits = __float_as_uint(v);
    g_Whi[i] = (u16)(bits >> 16);                             // truncation split (exact)
    float lo = v - __uint_as_float(bits & 0xFFFF0000u);
    __nv_bfloat16 lb = __float2bfloat16(lo);
    g_Wlo[i] = *(u16*)&lb;
}

// ---------------- PNA GEMM via mma.sync bf16 (3-term hi/lo split), pipelined --
// A[n,k] = [x | agg | s1*agg | s2*agg] built on the fly; A global loads
// register-staged ahead of compute; W tiles cp.async double-buffered.
template <int F, int FO, int FOP_, int NT, int WSTR, bool RELU>
__global__ void __launch_bounds__(256, 2) k_mma(const float* __restrict__ H,
                                                const float* __restrict__ Bias,
                                                float* __restrict__ OUT) {
    constexpr int K13 = 13 * F;
    constexpr int KT = K13 / 32;
    constexpr int ASTR = 40;               // 32 + 8 pad: conflict-free ldmatrix
    constexpr int F4 = 4 * F;
    constexpr int WCOLS = NT * 16;
    constexpr int WB = 32 * WSTR;          // u16 elems per W buffer
    __shared__ __align__(16) u16 sAhi[128 * ASTR];
    __shared__ __align__(16) u16 sAlo[128 * ASTR];
    __shared__ __align__(16) u16 sWhi[2][WB];
    __shared__ __align__(16) u16 sWlo[2][WB];
    __shared__ float sS1[128], sS2[128];

    int tid = threadIdx.x;
    int lane = tid & 31;
    int wid = tid >> 5;
    int warpM = wid & 3;
    int warpN = wid >> 2;
    int n0 = blockIdx.x * 128;

    if (tid < 128) {
        int n = n0 + tid;
        sS1[tid] = (n < NN) ? g_s1[n] : 0.f;
        sS2[tid] = (n < NN) ? g_s2[n] : 0.f;
    }
    if (FOP_ < WCOLS) {   // zero pad cols once in BOTH buffers (never rewritten)
        for (int i = tid; i < 32 * (WCOLS - FOP_); i += 256) {
            int kr = i / (WCOLS - FOP_);
            int c = FOP_ + i % (WCOLS - FOP_);
            sWhi[0][kr * WSTR + c] = 0; sWhi[1][kr * WSTR + c] = 0;
            sWlo[0][kr * WSTR + c] = 0; sWlo[1][kr * WSTR + c] = 0;
        }
    }

    uint32_t aAhi = smem_u32(sAhi), aAlo = smem_u32(sAlo);
    uint32_t aWhi0 = smem_u32(&sWhi[0][0]), aWlo0 = smem_u32(&sWlo[0][0]);

    float acc[2][NT][4];
#pragma unroll
    for (int m = 0; m < 2; m++)
#pragma unroll
        for (int n = 0; n < NT; n++)
#pragma unroll
            for (int j = 0; j < 4; j++) acc[m][n][j] = 0.f;

    // per-lane ldmatrix offsets (canonical x4 mapping)
    int q = lane >> 3, r = lane & 7;
    uint32_t aoff = (uint32_t)((warpM * 32 + (q & 1) * 8 + r) * ASTR + (q >> 1) * 8) * 2;
    uint32_t boff = (uint32_t)(((q & 1) * 8 + r) * WSTR + warpN * NT * 8 + (q >> 1) * 8) * 2;

    float2 pv[8];

    // --- stage helpers ---
    auto loadA = [&](int t) {
        int kb = t * 32;
#pragma unroll
        for (int p = 0; p < 8; p++) {
            int idx = tid + p * 256;
            int row = idx >> 4;
            int kp = idx & 15;
            int n = n0 + row;
            int k = kb + 2 * kp;
            float2 v = make_float2(0.f, 0.f);
            if (n < NN) {
                if (k < F) {
                    v = *(const float2*)&H[(size_t)n * F + k];
                } else {
                    int j = k - F;
                    float sc;
                    int jj;
                    if (j < F4)          { sc = 1.f;      jj = j; }
                    else if (j < 2 * F4) { sc = sS1[row]; jj = j - F4; }
                    else                 { sc = sS2[row]; jj = j - 2 * F4; }
                    float2 a = *(const float2*)&g_agg[(size_t)n * F4 + jj];
                    v.x = a.x * sc;
                    v.y = a.y * sc;
                }
            }
            pv[p] = v;
        }
    };
    auto storeA = [&]() {
#pragma unroll
        for (int p = 0; p < 8; p++) {
            int idx = tid + p * 256;
            int row = idx >> 4;
            int kp = idx & 15;
            float2 v = pv[p];
            uint32_t xi = __float_as_uint(v.x), yi = __float_as_uint(v.y);
            uint32_t hip = __byte_perm(xi, yi, 0x7632);
            float lx = v.x - __uint_as_float(xi & 0xFFFF0000u);
            float ly = v.y - __uint_as_float(yi & 0xFFFF0000u);
            __nv_bfloat162 lop = __floats2bfloat162_rn(lx, ly);
            *(uint32_t*)&sAhi[row * ASTR + 2 * kp] = hip;
            *(uint32_t*)&sAlo[row * ASTR + 2 * kp] = *(uint32_t*)&lop;
        }
    };
    auto cpW = [&](int t, int buf) {
        int kb = t * 32;
        constexpr int NU4 = 32 * FOP_ / 8;
        for (int i = tid; i < NU4; i += 256) {
            int kr = i / (FOP_ / 8);
            int ch = i - kr * (FOP_ / 8);
            uint32_t doff = (uint32_t)(kr * WSTR + ch * 8) * 2;
            size_t soff = (size_t)(kb + kr) * FOP_ + ch * 8;
            cpa16(aWhi0 + buf * (WB * 2) + doff, &g_Whi[soff]);
            cpa16(aWlo0 + buf * (WB * 2) + doff, &g_Wlo[soff]);
        }
    };

    // --- prologue: tile 0 ---
    loadA(0);
    cpW(0, 0);
    CPA_COMMIT();
    storeA();
    CPA_WAIT0();
    __syncthreads();

    for (int t = 0; t < KT; t++) {
        int cur = t & 1;
        if (t + 1 < KT) {
            loadA(t + 1);          // global loads issue now, consumed after sync
            cpW(t + 1, cur ^ 1);
            CPA_COMMIT();
        }
        uint32_t aW_hi = aWhi0 + cur * (WB * 2);
        uint32_t aW_lo = aWlo0 + cur * (WB * 2);
        // ---- compute: 2 k16 steps ----
#pragma unroll
        for (int ks = 0; ks < 32; ks += 16) {
            uint32_t ah[2][4], al[2][4];
            ldm_x4(ah[0], aAhi + aoff + 2 * ks);
            ldm_x4(ah[1], aAhi + aoff + 2 * ks + 16 * ASTR * 2);
            ldm_x4(al[0], aAlo + aoff + 2 * ks);
            ldm_x4(al[1], aAlo + aoff + 2 * ks + 16 * ASTR * 2);
            uint32_t bh[NT][2], bl[NT][2];
#pragma unroll
            for (int p2 = 0; p2 < NT / 2; p2++) {
                uint32_t r4[4];
                ldm_x4t(r4, aW_hi + boff + 2 * (ks * WSTR) + p2 * 32);
                bh[2 * p2][0] = r4[0]; bh[2 * p2][1] = r4[1];
                bh[2 * p2 + 1][0] = r4[2]; bh[2 * p2 + 1][1] = r4[3];
                ldm_x4t(r4, aW_lo + boff + 2 * (ks * WSTR) + p2 * 32);
                bl[2 * p2][0] = r4[0]; bl[2 * p2][1] = r4[1];
                bl[2 * p2 + 1][0] = r4[2]; bl[2 * p2 + 1][1] = r4[3];
            }
#pragma unroll
            for (int m = 0; m < 2; m++)
#pragma unroll
                for (int nt2 = 0; nt2 < NT; nt2++) {
                    mma_bf16(acc[m][nt2], ah[m], bh[nt2]);
                    mma_bf16(acc[m][nt2], al[m], bh[nt2]);
                    mma_bf16(acc[m][nt2], ah[m], bl[nt2]);
                }
        }
        __syncthreads();           // all warps done reading A buffer
        if (t + 1 < KT) storeA();  // write next A tile
        CPA_WAIT0();               // next W landed
        __syncthreads();
    }
    // ---- epilogue ----
    int gi = lane >> 2, ti = lane & 3;
#pragma unroll
    for (int m = 0; m < 2; m++) {
        int row0 = n0 + warpM * 32 + m * 16 + gi;
#pragma unroll
        for (int nt2 = 0; nt2 < NT; nt2++) {
            int col = warpN * NT * 8 + nt2 * 8 + ti * 2;
            if (col < FO) {   // FO even -> col+1 < FO too
                float b0v = Bias[col], b1v = Bias[col + 1];
                if (row0 < NN) {
                    float r0v = acc[m][nt2][0] + b0v;
                    float r1v = acc[m][nt2][1] + b1v;
                    if (RELU) { r0v = fmaxf(r0v, 0.f); r1v = fmaxf(r1v, 0.f); }
                    OUT[(size_t)row0 * FO + col] = r0v;
                    OUT[(size_t)row0 * FO + col + 1] = r1v;
                }
                if (row0 + 8 < NN) {
                    float r2v = acc[m][nt2][2] + b0v;
                    float r3v = acc[m][nt2][3] + b1v;
                    if (RELU) { r2v = fmaxf(r2v, 0.f); r3v = fmaxf(r3v, 0.f); }
                    OUT[(size_t)(row0 + 8) * FO + col] = r2v;
                    OUT[(size_t)(row0 + 8) * FO + col + 1] = r3v;
                }
            }
        }
    }
}

// ---------------- batchnorm ----------------
__global__ void k_bnzero() {
    int i = threadIdx.x;
    if (i < 128) { g_bnsum[i] = 0.f; g_bnssq[i] = 0.f; }
}

template <int C>
__global__ void k_bnstats(const float* __restrict__ h) {
    int c = threadIdx.x;
    if (c >= C) return;
    float s = 0.f, q = 0.f;
    for (int r = blockIdx.x; r < NN; r += gridDim.x) {
        float v = h[(size_t)r * C + c];
        s += v;
        q += v * v;
    }
    atomicAdd(&g_bnsum[c], s);
    atomicAdd(&g_bnssq[c], q);
}

template <int C>
__global__ void k_bnfin(const float* __restrict__ g, const float* __restrict__ be) {
    int c = threadIdx.x;
    if (c < C) {
        float mu = g_bnsum[c] / (float)NN;
        float var = g_bnssq[c] / (float)NN - mu * mu;
        float rs = rsqrtf(var + 1e-5f);
        float sc = g[c] * rs;
        g_scale[c] = sc;
        g_shift[c] = be[c] - mu * sc;
    }
}

template <int C, bool RELU>
__global__ void k_bnapply(float* __restrict__ h) {
    int i = blockIdx.x * 256 + threadIdx.x;
    if (i < NN * C) {
        int c = i % C;
        float v = h[i] * g_scale[c] + g_shift[c];
        if (RELU) v = fmaxf(v, 0.f);
        h[i] = v;
    }
}

// ---------------- pooling + head ----------------
__global__ void k_pool(const float* __restrict__ h, const int* __restrict__ batch) {
    int i = blockIdx.x * 256 + threadIdx.x;
    if (i < NN) {
        int g = batch[i];
        atomicAdd(&g_gcnt[g], 1);
        const float* row = h + (size_t)i * 20;
#pragma unroll
        for (int c = 0; c < 20; c++) {
            float v = row[c] * g_scale[c] + g_shift[c];
            atomicAdd(&g_zsum[g * 20 + c], v);
        }
    }
}

__global__ void k_final(const float* __restrict__ wl, const float* __restrict__ bl,
                        float* __restrict__ out, int out_size) {
    int g = threadIdx.x;
    if (g >= NGR) return;
    float inv = 1.f / fmaxf((float)g_gcnt[g], 1.f);
    float z[20];
#pragma unroll
    for (int c = 0; c < 20; c++) z[c] = g_zsum[g * 20 + c] * inv;
    float lo[11];
    float m = -3.4e38f;
#pragma unroll
    for (int o = 0; o < 11; o++) {
        float a = bl[o];
#pragma unroll
        for (int c = 0; c < 20; c++) a += z[c] * wl[c * 11 + o];
        lo[o] = a;
        m = fmaxf(m, a);
    }
    float ssum = 0.f;
#pragma unroll
    for (int o = 0; o < 11; o++) { lo[o] = expf(lo[o] - m); ssum += lo[o]; }
    float isum = 1.f / ssum;
#pragma unroll
    for (int o = 0; o < 11; o++) {
        int idx = g * 11 + o;
        if (idx < out_size) out[idx] = lo[o] * isum;
    }
#pragma unroll
    for (int c = 0; c < 20; c++) {
        int idx = NGR * 11 + g * 20 + c;
        if (idx < out_size) out[idx] = z[c];
    }
}

// ---------------- launcher ----------------
extern "C" void kernel_launch(void* const* d_in, const int* in_sizes, int n_in,
                              void* d_out, int out_size) {
    const float* x = (const float*)d_in[0];
    const int* ei = (const int*)d_in[1];
    const int* src = ei;
    const int* dst = ei + NE;
    const int* batch = (const int*)d_in[2];
    const float* w0 = (const float*)d_in[3];  const float* b0 = (const float*)d_in[4];
    const float* w1 = (const float*)d_in[5];  const float* b1 = (const float*)d_in[6];
    const float* w2 = (const float*)d_in[7];  const float* b2 = (const float*)d_in[8];
    const float* w3 = (const float*)d_in[9];  const float* b3 = (const float*)d_in[10];
    const float* g0 = (const float*)d_in[11]; const float* be0 = (const float*)d_in[12];
    const float* g1 = (const float*)d_in[13]; const float* be1 = (const float*)d_in[14];
    const float* g2 = (const float*)d_in[15]; const float* be2 = (const float*)d_in[16];
    const float* wl = (const float*)d_in[17]; const float* bl = (const float*)d_in[18];

    void* pA = 0; void* pB = 0;
    cudaGetSymbolAddress(&pA, g_hA);
    cudaGetSymbolAddress(&pB, g_hB);
    float* hA = (float*)pA;
    float* hB = (float*)pB;

    const int GB_E = (NE + 255) / 256;
    const int GB_N = (NN + 255) / 256;
    const int GB_M = (NN + 127) / 128;   // 782 blocks

    k_zero<<<GB_N, 256>>>();
    k_count<<<GB_E, 256>>>(dst);
    k_scan1<<<GB_N, 256>>>();
    k_scan2<<<1, 512>>>();
    k_scan3<<<GB_N, 256>>>();
    k_scatter<<<GB_E, 256>>>(src, dst);

    // layer 0: 64 -> 96, BN + relu
    k_agg<64><<<(NN * 32 + 255) / 256, 256>>>(x);
    k_wconv<832, 96, 96><<<(832 * 96 + 255) / 256, 256>>>(w0);
    k_mma<64, 96, 96, 6, 104, false><<<GB_M, 256>>>(x, b0, hA);
    k_bnzero<<<1, 128>>>();
    k_bnstats<96><<<512, 96>>>(hA);
    k_bnfin<96><<<1, 96>>>(g0, be0);
    k_bnapply<96, true><<<(NN * 96 + 255) / 256, 256>>>(hA);

    // layer 1: 96 -> 64, BN + relu
    k_agg<96><<<(NN * 32 + 255) / 256, 256>>>(hA);
    k_wconv<1248, 64, 64><<<(1248 * 64 + 255) / 256, 256>>>(w1);
    k_mma<96, 64, 64, 4, 72, false><<<GB_M, 256>>>(hA, b1, hB);
    k_bnzero<<<1, 128>>>();
    k_bnstats<64><<<512, 64>>>(hB);
    k_bnfin<64><<<1, 64>>>(g1, be1);
    k_bnapply<64, true><<<(NN * 64 + 255) / 256, 256>>>(hB);

    // layer 2: 64 -> 32, relu fused in epilogue
    k_agg<64><<<(NN * 32 + 255) / 256, 256>>>(hB);
    k_wconv<832, 32, 32><<<(832 * 32 + 255) / 256, 256>>>(w2);
    k_mma<64, 32, 32, 2, 40, true><<<GB_M, 256>>>(hB, b2, hA);

    // layer 3: 32 -> 20, BN affine fused into pooling
    k_agg<32><<<(NN * 32 + 255) / 256, 256>>>(hA);
    k_wconv<416, 20, 24><<<(416 * 24 + 255) / 256, 256>>>(w3);
    k_mma<32, 20, 24, 2, 40, false><<<GB_M, 256>>>(hA, b3, hB);
    k_bnzero<<<1, 128>>>();
    k_bnstats<20><<<512, 32>>>(hB);
    k_bnfin<20><<<1, 32>>>(g2, be2);

    k_pool<<<GB_N, 256>>>(hB, batch);
    k_final<<<1, 64>>>(wl, bl, (float*)d_out, out_size);
}

// round 8
// speedup vs baseline: 1.9485x; 1.0892x over previous
#include <cuda_runtime.h>
#include <cuda_bf16.h>
#include <math.h>
#include <stdint.h>

#define NN 100000
#define NE 3200000
#define NGR 64
typedef unsigned short u16;
static __device__ __constant__ float AVG_LOG_C = 3.4965076f; // log(33.0)

// ---------------- scratch (device globals; no allocations) ----------------
__device__ int   g_cnt[NN];
__device__ int   g_fill[NN];
__device__ int   g_rowstart[NN];
__device__ int   g_bsum[512];
__device__ int   g_boff[512];
__device__ int   g_srt[NE];
__device__ float g_s1[NN];
__device__ float g_s2[NN];
__device__ float g_hA[NN * 96];
__device__ float g_hB[NN * 96];
__device__ float g_agg[NN * 384];
__device__ __align__(16) u16 g_Whi[81920];
__device__ __align__(16) u16 g_Wlo[81920];
__device__ float g_bnsum[128];
__device__ float g_bnssq[128];
__device__ float g_scale[128];
__device__ float g_shift[128];
__device__ float g_zsum[NGR * 20];
__device__ int   g_gcnt[NGR];

// ---------------- helpers (sm_80+ portable) ----------------
__device__ __forceinline__ uint32_t smem_u32(const void* p) {
    uint32_t a;
    asm("{ .reg .u64 t; cvta.to.shared.u64 t, %1; cvt.u32.u64 %0, t; }" : "=r"(a) : "l"(p));
    return a;
}
__device__ __forceinline__ void ldm_x4(uint32_t* r, uint32_t addr) {
    asm volatile("ldmatrix.sync.aligned.m8n8.x4.shared.b16 {%0,%1,%2,%3}, [%4];"
        : "=r"(r[0]), "=r"(r[1]), "=r"(r[2]), "=r"(r[3]) : "r"(addr));
}
__device__ __forceinline__ void ldm_x4t(uint32_t* r, uint32_t addr) {
    asm volatile("ldmatrix.sync.aligned.m8n8.x4.trans.shared.b16 {%0,%1,%2,%3}, [%4];"
        : "=r"(r[0]), "=r"(r[1]), "=r"(r[2]), "=r"(r[3]) : "r"(addr));
}
__device__ __forceinline__ void mma_bf16(float* d, const uint32_t* a, const uint32_t* b) {
    asm volatile(
        "mma.sync.aligned.m16n8k16.row.col.f32.bf16.bf16.f32 "
        "{%0,%1,%2,%3}, {%4,%5,%6,%7}, {%8,%9}, {%0,%1,%2,%3};"
        : "+f"(d[0]), "+f"(d[1]), "+f"(d[2]), "+f"(d[3])
        : "r"(a[0]), "r"(a[1]), "r"(a[2]), "r"(a[3]), "r"(b[0]), "r"(b[1]));
}
__device__ __forceinline__ void cpa16(uint32_t dst, const void* src) {
    asm volatile("cp.async.cg.shared.global [%0], [%1], 16;" :: "r"(dst), "l"(src));
}
#define CPA_COMMIT() asm volatile("cp.async.commit_group;" ::: "memory")
#define CPA_WAIT0()  asm volatile("cp.async.wait_group 0;" ::: "memory")

// ---------------- graph preprocessing ----------------
__global__ void k_zero() {
    int i = blockIdx.x * 256 + threadIdx.x;
    if (i < NN) g_cnt[i] = 0;
    if (i < NGR * 20) g_zsum[i] = 0.f;
    if (i < NGR) g_gcnt[i] = 0;
}

__global__ void k_count(const int* __restrict__ dst) {
    int i = blockIdx.x * 256 + threadIdx.x;
    if (i < NE) atomicAdd(&g_cnt[dst[i]], 1);
}

__global__ void k_scan1() {
    __shared__ int s[256];
    int tid = threadIdx.x;
    int i = blockIdx.x * 256 + tid;
    s[tid] = (i < NN) ? g_cnt[i] : 0;
    __syncthreads();
    for (int off = 128; off > 0; off >>= 1) {
        if (tid < off) s[tid] += s[tid + off];
        __syncthreads();
    }
    if (tid == 0) g_bsum[blockIdx.x] = s[0];
}

__global__ void k_scan2() {
    __shared__ int s[512];
    int tid = threadIdx.x;
    int v = (tid < 391) ? g_bsum[tid] : 0;
    s[tid] = v;
    __syncthreads();
    for (int off = 1; off < 512; off <<= 1) {
        int t = (tid >= off) ? s[tid - off] : 0;
        __syncthreads();
        s[tid] += t;
        __syncthreads();
    }
    g_boff[tid] = s[tid] - v;
}

// scan3 + prep fused: rowstart, fill=rowstart, degree scalers
__global__ void k_scan3() {
    __shared__ int s[256];
    int tid = threadIdx.x;
    int i = blockIdx.x * 256 + tid;
    int v = (i < NN) ? g_cnt[i] : 0;
    s[tid] = v;
    __syncthreads();
    for (int off = 1; off < 256; off <<= 1) {
        int t = (tid >= off) ? s[tid - off] : 0;
        __syncthreads();
        s[tid] += t;
        __syncthreads();
    }
    if (i < NN) {
        int rs = g_boff[blockIdx.x] + s[tid] - v;
        g_rowstart[i] = rs;
        g_fill[i] = rs;
        int deg = v;
        float degc = (float)(deg > 1 ? deg : 1);
        float logd = logf(degc + 1.f);
        g_s1[i] = logd / AVG_LOG_C;
        g_s2[i] = AVG_LOG_C / logd;
    }
}

__global__ void k_scatter(const int* __restrict__ src, const int* __restrict__ dst) {
    int i = blockIdx.x * 256 + threadIdx.x;
    if (i < NE) {
        int d = dst[i];
        int p = atomicAdd(&g_fill[d], 1);
        g_srt[p] = src[i];
    }
}

// ---------------- per-node segmented aggregation (warp per node) ------------
// BN: apply y = relu(scale[f]*x + shift[f]) to each gathered value first.
template <int F, bool BN>
__global__ void __launch_bounds__(256) k_agg(const float* __restrict__ H) {
    constexpr int FPT = F / 32;
    int wid = (blockIdx.x * 256 + threadIdx.x) >> 5;
    int lane = threadIdx.x & 31;
    if (wid >= NN) return;
    int n = wid;
    int deg = g_cnt[n];
    int st = g_rowstart[n];
    float sc[FPT], sh[FPT];
    if (BN) {
#pragma unroll
        for (int i = 0; i < FPT; i++) { sc[i] = g_scale[lane + 32 * i]; sh[i] = g_shift[lane + 32 * i]; }
    }
    float sum[FPT], ssq[FPT], mn[FPT], mx[FPT];
#pragma unroll
    for (int i = 0; i < FPT; i++) { sum[i] = 0.f; ssq[i] = 0.f; mn[i] = 3.4e38f; mx[i] = -3.4e38f; }
    int e = 0;
    for (; e + 8 <= deg; e += 8) {
        int sidx[8];
#pragma unroll
        for (int u = 0; u < 8; u++) sidx[u] = g_srt[st + e + u];
#pragma unroll
        for (int i = 0; i < FPT; i++) {
            int f = lane + 32 * i;
            float v[8];
#pragma unroll
            for (int u = 0; u < 8; u++) v[u] = H[(size_t)sidx[u] * F + f];
#pragma unroll
            for (int u = 0; u < 8; u++) {
                if (BN) v[u] = fmaxf(fmaf(v[u], sc[i], sh[i]), 0.f);
                sum[i] += v[u];
                ssq[i] = fmaf(v[u], v[u], ssq[i]);
                mn[i] = fminf(mn[i], v[u]);
                mx[i] = fmaxf(mx[i], v[u]);
            }
        }
    }
    for (; e + 4 <= deg; e += 4) {
        int s0 = g_srt[st + e + 0];
        int s1 = g_srt[st + e + 1];
        int s2 = g_srt[st + e + 2];
        int s3 = g_srt[st + e + 3];
#pragma unroll
        for (int i = 0; i < FPT; i++) {
            int f = lane + 32 * i;
            float v0 = H[(size_t)s0 * F + f], v1 = H[(size_t)s1 * F + f];
            float v2 = H[(size_t)s2 * F + f], v3 = H[(size_t)s3 * F + f];
            if (BN) {
                v0 = fmaxf(fmaf(v0, sc[i], sh[i]), 0.f);
                v1 = fmaxf(fmaf(v1, sc[i], sh[i]), 0.f);
                v2 = fmaxf(fmaf(v2, sc[i], sh[i]), 0.f);
                v3 = fmaxf(fmaf(v3, sc[i], sh[i]), 0.f);
            }
            sum[i] += v0 + v1 + v2 + v3;
            ssq[i] += v0 * v0 + v1 * v1 + v2 * v2 + v3 * v3;
            mn[i] = fminf(mn[i], fminf(fminf(v0, v1), fminf(v2, v3)));
            mx[i] = fmaxf(mx[i], fmaxf(fmaxf(v0, v1), fmaxf(v2, v3)));
        }
    }
    for (; e < deg; e++) {
        int s = g_srt[st + e];
#pragma unroll
        for (int i = 0; i < FPT; i++) {
            float v = H[(size_t)s * F + lane + 32 * i];
            if (BN) v = fmaxf(fmaf(v, sc[i], sh[i]), 0.f);
            sum[i] += v;
            ssq[i] += v * v;
            mn[i] = fminf(mn[i], v);
            mx[i] = fmaxf(mx[i], v);
        }
    }
    float inv = 1.f / (float)(deg > 1 ? deg : 1);
    float* out = g_agg + (size_t)n * (4 * F);
#pragma unroll
    for (int i = 0; i < FPT; i++) {
        int f = lane + 32 * i;
        float mean = sum[i] * inv;
        float msq = ssq[i] * inv;
        float sd = sqrtf(fmaxf(msq - mean * mean, 0.f) + 1e-5f);
        float lmn = (deg > 0) ? mn[i] : 0.f;
        float lmx = (deg > 0) ? mx[i] : 0.f;
        out[f] = mean;
        out[F + f] = lmn;
        out[2 * F + f] = lmx;
        out[3 * F + f] = sd;
    }
}

// -------- W pre-conversion (also zeroes BN accumulators for the next GEMM) --
template <int K13, int FO, int FOP_>
__global__ void k_wconv(const float* __restrict__ W) {
    int i = blockIdx.x * 256 + threadIdx.x;
    if (blockIdx.x == 0 && threadIdx.x < 128) { g_bnsum[threadIdx.x] = 0.f; g_bnssq[threadIdx.x] = 0.f; }
    if (i >= K13 * FOP_) return;
    int k = i / FOP_;
    int c = i - k * FOP_;
    float v = (c < FO) ? W[(size_t)k * FO + c] : 0.f;
    uint32_t bits = __float_as_uint(v);
    g_Whi[i] = (u16)(bits >> 16);                             // truncation split (exact)
    float lo = v - __uint_as_float(bits & 0xFFFF0000u);
    __nv_bfloat16 lb = __float2bfloat16(lo);
    g_Wlo[i] = *(u16*)&lb;
}

// ---------------- PNA GEMM via mma.sync bf16 (3-term hi/lo split), pipelined --
// BNIN: apply relu(scale*h+shift) to self-feature reads.
// STATS: accumulate per-column sum/sumsq of outputs into g_bnsum/g_bnssq.
template <int F, int FO, int FOP_, int NT, int WSTR, bool RELU, bool BNIN, bool STATS>
__global__ void __launch_bounds__(256, 2) k_mma(const float* __restrict__ H,
                                                const float* __restrict__ Bias,
                                                float* __restrict__ OUT) {
    constexpr int K13 = 13 * F;
    constexpr int KT = K13 / 32;
    constexpr int ASTR = 40;               // 32 + 8 pad: conflict-free ldmatrix
    constexpr int F4 = 4 * F;
    constexpr int WCOLS = NT * 16;
    constexpr int WB = 32 * WSTR;          // u16 elems per W buffer
    __shared__ __align__(16) u16 sAhi[128 * ASTR];
    __shared__ __align__(16) u16 sAlo[128 * ASTR];
    __shared__ __align__(16) u16 sWhi[2][WB];
    __shared__ __align__(16) u16 sWlo[2][WB];
    __shared__ float sS1[128], sS2[128];

    int tid = threadIdx.x;
    int lane = tid & 31;
    int wid = tid >> 5;
    int warpM = wid & 3;
    int warpN = wid >> 2;
    int n0 = blockIdx.x * 128;

    if (tid < 128) {
        int n = n0 + tid;
        sS1[tid] = (n < NN) ? g_s1[n] : 0.f;
        sS2[tid] = (n < NN) ? g_s2[n] : 0.f;
    }
    if (FOP_ < WCOLS) {   // zero pad cols once in BOTH buffers (never rewritten)
        for (int i = tid; i < 32 * (WCOLS - FOP_); i += 256) {
            int kr = i / (WCOLS - FOP_);
            int c = FOP_ + i % (WCOLS - FOP_);
            sWhi[0][kr * WSTR + c] = 0; sWhi[1][kr * WSTR + c] = 0;
            sWlo[0][kr * WSTR + c] = 0; sWlo[1][kr * WSTR + c] = 0;
        }
    }

    uint32_t aAhi = smem_u32(sAhi), aAlo = smem_u32(sAlo);
    uint32_t aWhi0 = smem_u32(&sWhi[0][0]), aWlo0 = smem_u32(&sWlo[0][0]);

    float acc[2][NT][4];
#pragma unroll
    for (int m = 0; m < 2; m++)
#pragma unroll
        for (int n = 0; n < NT; n++)
#pragma unroll
            for (int j = 0; j < 4; j++) acc[m][n][j] = 0.f;

    int q = lane >> 3, r = lane & 7;
    uint32_t aoff = (uint32_t)((warpM * 32 + (q & 1) * 8 + r) * ASTR + (q >> 1) * 8) * 2;
    uint32_t boff = (uint32_t)(((q & 1) * 8 + r) * WSTR + warpN * NT * 8 + (q >> 1) * 8) * 2;

    float2 pv[8];

    auto loadA = [&](int t) {
        int kb = t * 32;
#pragma unroll
        for (int p = 0; p < 8; p++) {
            int idx = tid + p * 256;
            int row = idx >> 4;
            int kp = idx & 15;
            int n = n0 + row;
            int k = kb + 2 * kp;
            float2 v = make_float2(0.f, 0.f);
            if (n < NN) {
                if (k < F) {
                    v = *(const float2*)&H[(size_t)n * F + k];
                    if (BNIN) {
                        float2 sc2 = *(const float2*)&g_scale[k];
                        float2 sh2 = *(const float2*)&g_shift[k];
                        v.x = fmaxf(fmaf(v.x, sc2.x, sh2.x), 0.f);
                        v.y = fmaxf(fmaf(v.y, sc2.y, sh2.y), 0.f);
                    }
                } else {
                    int j = k - F;
                    float sc;
                    int jj;
                    if (j < F4)          { sc = 1.f;      jj = j; }
                    else if (j < 2 * F4) { sc = sS1[row]; jj = j - F4; }
                    else                 { sc = sS2[row]; jj = j - 2 * F4; }
                    float2 a = *(const float2*)&g_agg[(size_t)n * F4 + jj];
                    v.x = a.x * sc;
                    v.y = a.y * sc;
                }
            }
            pv[p] = v;
        }
    };
    auto storeA = [&]() {
#pragma unroll
        for (int p = 0; p < 8; p++) {
            int idx = tid + p * 256;
            int row = idx >> 4;
            int kp = idx & 15;
            float2 v = pv[p];
            uint32_t xi = __float_as_uint(v.x), yi = __float_as_uint(v.y);
            uint32_t hip = __byte_perm(xi, yi, 0x7632);
            float lx = v.x - __uint_as_float(xi & 0xFFFF0000u);
            float ly = v.y - __uint_as_float(yi & 0xFFFF0000u);
            __nv_bfloat162 lop = __floats2bfloat162_rn(lx, ly);
            *(uint32_t*)&sAhi[row * ASTR + 2 * kp] = hip;
            *(uint32_t*)&sAlo[row * ASTR + 2 * kp] = *(uint32_t*)&lop;
        }
    };
    auto cpW = [&](int t, int buf) {
        int kb = t * 32;
        constexpr int NU4 = 32 * FOP_ / 8;
        for (int i = tid; i < NU4; i += 256) {
            int kr = i / (FOP_ / 8);
            int ch = i - kr * (FOP_ / 8);
            uint32_t doff = (uint32_t)(kr * WSTR + ch * 8) * 2;
            size_t soff = (size_t)(kb + kr) * FOP_ + ch * 8;
            cpa16(aWhi0 + buf * (WB * 2) + doff, &g_Whi[soff]);
            cpa16(aWlo0 + buf * (WB * 2) + doff, &g_Wlo[soff]);
        }
    };

    loadA(0);
    cpW(0, 0);
    CPA_COMMIT();
    storeA();
    CPA_WAIT0();
    __syncthreads();

    for (int t = 0; t < KT; t++) {
        int cur = t & 1;
        if (t + 1 < KT) {
            loadA(t + 1);
            cpW(t + 1, cur ^ 1);
            CPA_COMMIT();
        }
        uint32_t aW_hi = aWhi0 + cur * (WB * 2);
        uint32_t aW_lo = aWlo0 + cur * (WB * 2);
#pragma unroll
        for (int ks = 0; ks < 32; ks += 16) {
            uint32_t ah[2][4], al[2][4];
            ldm_x4(ah[0], aAhi + aoff + 2 * ks);
            ldm_x4(ah[1], aAhi + aoff + 2 * ks + 16 * ASTR * 2);
            ldm_x4(al[0], aAlo + aoff + 2 * ks);
            ldm_x4(al[1], aAlo + aoff + 2 * ks + 16 * ASTR * 2);
            uint32_t bh[NT][2], bl[NT][2];
#pragma unroll
            for (int p2 = 0; p2 < NT / 2; p2++) {
                uint32_t r4[4];
                ldm_x4t(r4, aW_hi + boff + 2 * (ks * WSTR) + p2 * 32);
                bh[2 * p2][0] = r4[0]; bh[2 * p2][1] = r4[1];
                bh[2 * p2 + 1][0] = r4[2]; bh[2 * p2 + 1][1] = r4[3];
                ldm_x4t(r4, aW_lo + boff + 2 * (ks * WSTR) + p2 * 32);
                bl[2 * p2][0] = r4[0]; bl[2 * p2][1] = r4[1];
                bl[2 * p2 + 1][0] = r4[2]; bl[2 * p2 + 1][1] = r4[3];
            }
#pragma unroll
            for (int m = 0; m < 2; m++)
#pragma unroll
                for (int nt2 = 0; nt2 < NT; nt2++) {
                    mma_bf16(acc[m][nt2], ah[m], bh[nt2]);
                    mma_bf16(acc[m][nt2], al[m], bh[nt2]);
                    mma_bf16(acc[m][nt2], ah[m], bl[nt2]);
                }
        }
        __syncthreads();
        if (t + 1 < KT) storeA();
        CPA_WAIT0();
        __syncthreads();
    }
    // ---- epilogue (+ optional BN stats) ----
    int gi = lane >> 2, ti = lane & 3;
    float cs[NT][2], cq[NT][2];
    if (STATS) {
#pragma unroll
        for (int n = 0; n < NT; n++) { cs[n][0] = 0.f; cs[n][1] = 0.f; cq[n][0] = 0.f; cq[n][1] = 0.f; }
    }
#pragma unroll
    for (int m = 0; m < 2; m++) {
        int row0 = n0 + warpM * 32 + m * 16 + gi;
#pragma unroll
        for (int nt2 = 0; nt2 < NT; nt2++) {
            int col = warpN * NT * 8 + nt2 * 8 + ti * 2;
            if (col < FO) {
                float b0v = Bias[col], b1v = Bias[col + 1];
                if (row0 < NN) {
                    float r0v = acc[m][nt2][0] + b0v;
                    float r1v = acc[m][nt2][1] + b1v;
                    if (RELU) { r0v = fmaxf(r0v, 0.f); r1v = fmaxf(r1v, 0.f); }
                    OUT[(size_t)row0 * FO + col] = r0v;
                    OUT[(size_t)row0 * FO + col + 1] = r1v;
                    if (STATS) {
                        cs[nt2][0] += r0v; cq[nt2][0] += r0v * r0v;
                        cs[nt2][1] += r1v; cq[nt2][1] += r1v * r1v;
                    }
                }
                if (row0 + 8 < NN) {
                    float r2v = acc[m][nt2][2] + b0v;
                    float r3v = acc[m][nt2][3] + b1v;
                    if (RELU) { r2v = fmaxf(r2v, 0.f); r3v = fmaxf(r3v, 0.f); }
                    OUT[(size_t)(row0 + 8) * FO + col] = r2v;
                    OUT[(size_t)(row0 + 8) * FO + col + 1] = r3v;
                    if (STATS) {
                        cs[nt2][0] += r2v; cq[nt2][0] += r2v * r2v;
                        cs[nt2][1] += r3v; cq[nt2][1] += r3v * r3v;
                    }
                }
            }
        }
    }
    if (STATS) {
        __syncthreads();                       // main loop fully done; reuse sS1/sS2
        for (int i = tid; i < FO; i += 256) { sS1[i] = 0.f; sS2[i] = 0.f; }
        __syncthreads();
#pragma unroll
        for (int nt2 = 0; nt2 < NT; nt2++)
#pragma unroll
            for (int j = 0; j < 2; j++) {
                float v = cs[nt2][j], qv = cq[nt2][j];
                v += __shfl_xor_sync(0xFFFFFFFFu, v, 4);
                qv += __shfl_xor_sync(0xFFFFFFFFu, qv, 4);
                v += __shfl_xor_sync(0xFFFFFFFFu, v, 8);
                qv += __shfl_xor_sync(0xFFFFFFFFu, qv, 8);
                v += __shfl_xor_sync(0xFFFFFFFFu, v, 16);
                qv += __shfl_xor_sync(0xFFFFFFFFu, qv, 16);
                if (gi == 0) {                 // lanes 0..3 hold totals over gi
                    int col = warpN * NT * 8 + nt2 * 8 + ti * 2 + j;
                    if (col < FO) {
                        atomicAdd(&sS1[col], v);
                        atomicAdd(&sS2[col], qv);
                    }
                }
            }
        __syncthreads();
        for (int i = tid; i < FO; i += 256) {
            atomicAdd(&g_bnsum[i], sS1[i]);
            atomicAdd(&g_bnssq[i], sS2[i]);
        }
    }
}

// ---------------- BN finalize ----------------
template <int C>
__global__ void k_bnfin(const float* __restrict__ g, const float* __restrict__ be) {
    int c = threadIdx.x;
    if (c < C) {
        float mu = g_bnsum[c] / (float)NN;
        float var = g_bnssq[c] / (float)NN - mu * mu;
        float rs = rsqrtf(var + 1e-5f);
        float sc = g[c] * rs;
        g_scale[c] = sc;
        g_shift[c] = be[c] - mu * sc;
    }
}

// ---------------- pooling + head ----------------
__global__ void k_pool(const float* __restrict__ h, const int* __restrict__ batch) {
    int i = blockIdx.x * 256 + threadIdx.x;
    if (i < NN) {
        int g = batch[i];
        atomicAdd(&g_gcnt[g], 1);
        const float* row = h + (size_t)i * 20;
#pragma unroll
        for (int c = 0; c < 20; c++) {
            float v = row[c] * g_scale[c] + g_shift[c];
            atomicAdd(&g_zsum[g * 20 + c], v);
        }
    }
}

__global__ void k_final(const float* __restrict__ wl, const float* __restrict__ bl,
                        float* __restrict__ out, int out_size) {
    int g = threadIdx.x;
    if (g >= NGR) return;
    float inv = 1.f / fmaxf((float)g_gcnt[g], 1.f);
    float z[20];
#pragma unroll
    for (int c = 0; c < 20; c++) z[c] = g_zsum[g * 20 + c] * inv;
    float lo[11];
    float m = -3.4e38f;
#pragma unroll
    for (int o = 0; o < 11; o++) {
        float a = bl[o];
#pragma unroll
        for (int c = 0; c < 20; c++) a += z[c] * wl[c * 11 + o];
        lo[o] = a;
        m = fmaxf(m, a);
    }
    float ssum = 0.f;
#pragma unroll
    for (int o = 0; o < 11; o++) { lo[o] = expf(lo[o] - m); ssum += lo[o]; }
    float isum = 1.f / ssum;
#pragma unroll
    for (int o = 0; o < 11; o++) {
        int idx = g * 11 + o;
        if (idx < out_size) out[idx] = lo[o] * isum;
    }
#pragma unroll
    for (int c = 0; c < 20; c++) {
        int idx = NGR * 11 + g * 20 + c;
        if (idx < out_size) out[idx] = z[c];
    }
}

// ---------------- launcher ----------------
extern "C" void kernel_launch(void* const* d_in, const int* in_sizes, int n_in,
                              void* d_out, int out_size) {
    const float* x = (const float*)d_in[0];
    const int* ei = (const int*)d_in[1];
    const int* src = ei;
    const int* dst = ei + NE;
    const int* batch = (const int*)d_in[2];
    const float* w0 = (const float*)d_in[3];  const float* b0 = (const float*)d_in[4];
    const float* w1 = (const float*)d_in[5];  const float* b1 = (const float*)d_in[6];
    const float* w2 = (const float*)d_in[7];  const float* b2 = (const float*)d_in[8];
    const float* w3 = (const float*)d_in[9];  const float* b3 = (const float*)d_in[10];
    const float* g0 = (const float*)d_in[11]; const float* be0 = (const float*)d_in[12];
    const float* g1 = (const float*)d_in[13]; const float* be1 = (const float*)d_in[14];
    const float* g2 = (const float*)d_in[15]; const float* be2 = (const float*)d_in[16];
    const float* wl = (const float*)d_in[17]; const float* bl = (const float*)d_in[18];

    void* pA = 0; void* pB = 0;
    cudaGetSymbolAddress(&pA, g_hA);
    cudaGetSymbolAddress(&pB, g_hB);
    float* hA = (float*)pA;
    float* hB = (float*)pB;

    const int GB_E = (NE + 255) / 256;
    const int GB_N = (NN + 255) / 256;
    const int GB_M = (NN + 127) / 128;   // 782 blocks

    k_zero<<<GB_N, 256>>>();
    k_count<<<GB_E, 256>>>(dst);
    k_scan1<<<GB_N, 256>>>();
    k_scan2<<<1, 512>>>();
    k_scan3<<<GB_N, 256>>>();
    k_scatter<<<GB_E, 256>>>(src, dst);

    // layer 0: 64 -> 96, BN stats fused in epilogue
    k_agg<64, false><<<(NN * 32 + 255) / 256, 256>>>(x);
    k_wconv<832, 96, 96><<<(832 * 96 + 255) / 256, 256>>>(w0);
    k_mma<64, 96, 96, 6, 104, false, false, true><<<GB_M, 256>>>(x, b0, hA);
    k_bnfin<96><<<1, 96>>>(g0, be0);

    // layer 1: 96 -> 64; BN0 applied on the fly in agg + A-build
    k_agg<96, true><<<(NN * 32 + 255) / 256, 256>>>(hA);
    k_wconv<1248, 64, 64><<<(1248 * 64 + 255) / 256, 256>>>(w1);
    k_mma<96, 64, 64, 4, 72, false, true, true><<<GB_M, 256>>>(hA, b1, hB);
    k_bnfin<64><<<1, 64>>>(g1, be1);

    // layer 2: 64 -> 32; BN1 applied on the fly; relu in epilogue
    k_agg<64, true><<<(NN * 32 + 255) / 256, 256>>>(hB);
    k_wconv<832, 32, 32><<<(832 * 32 + 255) / 256, 256>>>(w2);
    k_mma<64, 32, 32, 2, 40, true, true, false><<<GB_M, 256>>>(hB, b2, hA);

    // layer 3: 32 -> 20; BN2 stats fused; affine applied in pooling
    k_agg<32, false><<<(NN * 32 + 255) / 256, 256>>>(hA);
    k_wconv<416, 20, 24><<<(416 * 24 + 255) / 256, 256>>>(w3);
    k_mma<32, 20, 24, 2, 40, false, false, true><<<GB_M, 256>>>(hA, b3, hB);
    k_bnfin<20><<<1, 32>>>(g2, be2);

    k_pool<<<GB_N, 256>>>(hB, batch);
    k_final<<<1, 64>>>(wl, bl, (float*)d_out, out_size);
}

// round 10
// speedup vs baseline: 2.0931x; 1.0742x over previous
#include <cuda_runtime.h>
#include <cuda_bf16.h>
#include <math.h>
#include <stdint.h>

#define NN 100000
#define NE 3200000
#define NGR 64
typedef unsigned short u16;
static __device__ __constant__ float AVG_LOG_C = 3.4965076f; // log(33.0)

// ---------------- scratch (device globals; no allocations) ----------------
__device__ int   g_cnt[NN];
__device__ int   g_fill[NN];
__device__ int   g_rowstart[NN];
__device__ int   g_bsum[512];
__device__ int   g_boff[512];
__device__ int   g_srt[NE];
__device__ float g_s1[NN];
__device__ float g_s2[NN];
__device__ float g_hA[NN * 96];
__device__ float g_hB[NN * 96];
__device__ __align__(16) float g_agg[NN * 384];
__device__ __align__(16) u16 g_Whi[81920];
__device__ __align__(16) u16 g_Wlo[81920];
__device__ float g_bnsum[128];
__device__ float g_bnssq[128];
__device__ __align__(16) float g_scale[128];
__device__ __align__(16) float g_shift[128];
__device__ float g_zsum[NGR * 20];
__device__ int   g_gcnt[NGR];

// ---------------- helpers (sm_80+ portable) ----------------
__device__ __forceinline__ uint32_t smem_u32(const void* p) {
    uint32_t a;
    asm("{ .reg .u64 t; cvta.to.shared.u64 t, %1; cvt.u32.u64 %0, t; }" : "=r"(a) : "l"(p));
    return a;
}
__device__ __forceinline__ void ldm_x4(uint32_t* r, uint32_t addr) {
    asm volatile("ldmatrix.sync.aligned.m8n8.x4.shared.b16 {%0,%1,%2,%3}, [%4];"
        : "=r"(r[0]), "=r"(r[1]), "=r"(r[2]), "=r"(r[3]) : "r"(addr));
}
__device__ __forceinline__ void ldm_x4t(uint32_t* r, uint32_t addr) {
    asm volatile("ldmatrix.sync.aligned.m8n8.x4.trans.shared.b16 {%0,%1,%2,%3}, [%4];"
        : "=r"(r[0]), "=r"(r[1]), "=r"(r[2]), "=r"(r[3]) : "r"(addr));
}
__device__ __forceinline__ void mma_bf16(float* d, const uint32_t* a, const uint32_t* b) {
    asm volatile(
        "mma.sync.aligned.m16n8k16.row.col.f32.bf16.bf16.f32 "
        "{%0,%1,%2,%3}, {%4,%5,%6,%7}, {%8,%9}, {%0,%1,%2,%3};"
        : "+f"(d[0]), "+f"(d[1]), "+f"(d[2]), "+f"(d[3])
        : "r"(a[0]), "r"(a[1]), "r"(a[2]), "r"(a[3]), "r"(b[0]), "r"(b[1]));
}
__device__ __forceinline__ void cpa16(uint32_t dst, const void* src) {
    asm volatile("cp.async.cg.shared.global [%0], [%1], 16;" :: "r"(dst), "l"(src));
}
#define CPA_COMMIT() asm volatile("cp.async.commit_group;" ::: "memory")
#define CPA_WAIT0()  asm volatile("cp.async.wait_group 0;" ::: "memory")

// ---------------- graph preprocessing ----------------
__global__ void k_count(const int* __restrict__ dst) {
    int i = blockIdx.x * 256 + threadIdx.x;
    if (i < NE) atomicAdd(&g_cnt[dst[i]], 1);
}

__global__ void k_scan1() {
    __shared__ int s[256];
    int tid = threadIdx.x;
    int i = blockIdx.x * 256 + tid;
    s[tid] = (i < NN) ? g_cnt[i] : 0;
    __syncthreads();
    for (int off = 128; off > 0; off >>= 1) {
        if (tid < off) s[tid] += s[tid + off];
        __syncthreads();
    }
    if (tid == 0) g_bsum[blockIdx.x] = s[0];
}

__global__ void k_scan2() {
    __shared__ int s[512];
    int tid = threadIdx.x;
    int v = (tid < 391) ? g_bsum[tid] : 0;
    s[tid] = v;
    __syncthreads();
    for (int off = 1; off < 512; off <<= 1) {
        int t = (tid >= off) ? s[tid - off] : 0;
        __syncthreads();
        s[tid] += t;
        __syncthreads();
    }
    g_boff[tid] = s[tid] - v;
}

// scan3 + prep fused: rowstart, fill=rowstart, degree scalers
__global__ void k_scan3() {
    __shared__ int s[256];
    int tid = threadIdx.x;
    int i = blockIdx.x * 256 + tid;
    int v = (i < NN) ? g_cnt[i] : 0;
    s[tid] = v;
    __syncthreads();
    for (int off = 1; off < 256; off <<= 1) {
        int t = (tid >= off) ? s[tid - off] : 0;
        __syncthreads();
        s[tid] += t;
        __syncthreads();
    }
    if (i < NN) {
        int rs = g_boff[blockIdx.x] + s[tid] - v;
        g_rowstart[i] = rs;
        g_fill[i] = rs;
        int deg = v;
        float degc = (float)(deg > 1 ? deg : 1);
        float logd = logf(degc + 1.f);
        g_s1[i] = logd / AVG_LOG_C;
        g_s2[i] = AVG_LOG_C / logd;
    }
}

__global__ void k_scatter(const int* __restrict__ src, const int* __restrict__ dst) {
    int i = blockIdx.x * 256 + threadIdx.x;
    if (i < NE) {
        int d = dst[i];
        int p = atomicAdd(&g_fill[d], 1);
        g_srt[p] = src[i];
    }
}

// ---------------- per-node segmented aggregation (warp per node) ------------
// F in {32, 64}: vectorized float4 path — warp split into 32/(F/4) edge-groups,
// one LDG.128 per lane per edge; shfl-combine across groups at the end.
// F == 96: scalar path (3 floats/lane), 8-edge unroll.
// BN: apply y = relu(scale[f]*x + shift[f]) to each gathered value first.
template <int F, bool BN>
__global__ void __launch_bounds__(256) k_agg(const float* __restrict__ H) {
    int wid = (blockIdx.x * 256 + threadIdx.x) >> 5;
    int lane = threadIdx.x & 31;
    if (wid >= NN) return;
    int n = wid;
    int deg = g_cnt[n];
    int st = g_rowstart[n];

    if constexpr (F != 96) {
        constexpr int QPR = F / 4;      // quads per row: 16 (F=64) / 8 (F=32)
        constexpr int NG = 32 / QPR;    // edge-groups per warp: 2 / 4
        constexpr int U = 8;            // batches in flight
        int grp = lane / QPR;
        int fl = lane - grp * QPR;
        float4 sc4, sh4;
        if (BN) {
            sc4 = *(const float4*)&g_scale[fl * 4];
            sh4 = *(const float4*)&g_shift[fl * 4];
        }
        float4 sum = make_float4(0.f, 0.f, 0.f, 0.f);
        float4 ssq = make_float4(0.f, 0.f, 0.f, 0.f);
        float4 mn = make_float4(3.4e38f, 3.4e38f, 3.4e38f, 3.4e38f);
        float4 mx = make_float4(-3.4e38f, -3.4e38f, -3.4e38f, -3.4e38f);
        auto accum = [&](float4 v) {
            if (BN) {
                v.x = fmaxf(fmaf(v.x, sc4.x, sh4.x), 0.f);
                v.y = fmaxf(fmaf(v.y, sc4.y, sh4.y), 0.f);
                v.z = fmaxf(fmaf(v.z, sc4.z, sh4.z), 0.f);
                v.w = fmaxf(fmaf(v.w, sc4.w, sh4.w), 0.f);
            }
            sum.x += v.x; sum.y += v.y; sum.z += v.z; sum.w += v.w;
            ssq.x = fmaf(v.x, v.x, ssq.x); ssq.y = fmaf(v.y, v.y, ssq.y);
            ssq.z = fmaf(v.z, v.z, ssq.z); ssq.w = fmaf(v.w, v.w, ssq.w);
            mn.x = fminf(mn.x, v.x); mn.y = fminf(mn.y, v.y);
            mn.z = fminf(mn.z, v.z); mn.w = fminf(mn.w, v.w);
            mx.x = fmaxf(mx.x, v.x); mx.y = fmaxf(mx.y, v.y);
            mx.z = fmaxf(mx.z, v.z); mx.w = fmaxf(mx.w, v.w);
        };
        int e = 0;
        for (; e + U * NG <= deg; e += U * NG) {
            int sidx[U];
#pragma unroll
            for (int u = 0; u < U; u++) sidx[u] = g_srt[st + e + u * NG + grp];
#pragma unroll
            for (int u = 0; u < U; u++)
                accum(*(const float4*)&H[(size_t)sidx[u] * F + fl * 4]);
        }
        for (; e + NG <= deg; e += NG) {
            int s = g_srt[st + e + grp];
            accum(*(const float4*)&H[(size_t)s * F + fl * 4]);
        }
        int rem = deg - e;
        if (grp < rem) {
            int s = g_srt[st + e + grp];
            accum(*(const float4*)&H[(size_t)s * F + fl * 4]);
        }
        // combine across edge-groups
#pragma unroll
        for (int d = QPR; d < 32; d <<= 1) {
            sum.x += __shfl_xor_sync(0xFFFFFFFFu, sum.x, d);
            sum.y += __shfl_xor_sync(0xFFFFFFFFu, sum.y, d);
            sum.z += __shfl_xor_sync(0xFFFFFFFFu, sum.z, d);
            sum.w += __shfl_xor_sync(0xFFFFFFFFu, sum.w, d);
            ssq.x += __shfl_xor_sync(0xFFFFFFFFu, ssq.x, d);
            ssq.y += __shfl_xor_sync(0xFFFFFFFFu, ssq.y, d);
            ssq.z += __shfl_xor_sync(0xFFFFFFFFu, ssq.z, d);
            ssq.w += __shfl_xor_sync(0xFFFFFFFFu, ssq.w, d);
            mn.x = fminf(mn.x, __shfl_xor_sync(0xFFFFFFFFu, mn.x, d));
            mn.y = fminf(mn.y, __shfl_xor_sync(0xFFFFFFFFu, mn.y, d));
            mn.z = fminf(mn.z, __shfl_xor_sync(0xFFFFFFFFu, mn.z, d));
            mn.w = fminf(mn.w, __shfl_xor_sync(0xFFFFFFFFu, mn.w, d));
            mx.x = fmaxf(mx.x, __shfl_xor_sync(0xFFFFFFFFu, mx.x, d));
            mx.y = fmaxf(mx.y, __shfl_xor_sync(0xFFFFFFFFu, mx.y, d));
            mx.z = fmaxf(mx.z, __shfl_xor_sync(0xFFFFFFFFu, mx.z, d));
            mx.w = fmaxf(mx.w, __shfl_xor_sync(0xFFFFFFFFu, mx.w, d));
        }
        if (grp == 0) {
            float inv = 1.f / (float)(deg > 1 ? deg : 1);
            float4 mean, sd, lmn, lmx;
            mean.x = sum.x * inv; mean.y = sum.y * inv; mean.z = sum.z * inv; mean.w = sum.w * inv;
            sd.x = sqrtf(fmaxf(ssq.x * inv - mean.x * mean.x, 0.f) + 1e-5f);
            sd.y = sqrtf(fmaxf(ssq.y * inv - mean.y * mean.y, 0.f) + 1e-5f);
            sd.z = sqrtf(fmaxf(ssq.z * inv - mean.z * mean.z, 0.f) + 1e-5f);
            sd.w = sqrtf(fmaxf(ssq.w * inv - mean.w * mean.w, 0.f) + 1e-5f);
            bool has = deg > 0;
            lmn = has ? mn : make_float4(0.f, 0.f, 0.f, 0.f);
            lmx = has ? mx : make_float4(0.f, 0.f, 0.f, 0.f);
            float* out = g_agg + (size_t)n * (4 * F);
            *(float4*)&out[fl * 4] = mean;
            *(float4*)&out[F + fl * 4] = lmn;
            *(float4*)&out[2 * F + fl * 4] = lmx;
            *(float4*)&out[3 * F + fl * 4] = sd;
        }
    } else {
        constexpr int FPT = 3;
        float sc[FPT], sh[FPT];
        if (BN) {
#pragma unroll
            for (int i = 0; i < FPT; i++) { sc[i] = g_scale[lane + 32 * i]; sh[i] = g_shift[lane + 32 * i]; }
        }
        float sum[FPT], ssq[FPT], mn[FPT], mx[FPT];
#pragma unroll
        for (int i = 0; i < FPT; i++) { sum[i] = 0.f; ssq[i] = 0.f; mn[i] = 3.4e38f; mx[i] = -3.4e38f; }
        int e = 0;
        for (; e + 8 <= deg; e += 8) {
            int sidx[8];
#pragma unroll
            for (int u = 0; u < 8; u++) sidx[u] = g_srt[st + e + u];
#pragma unroll
            for (int i = 0; i < FPT; i++) {
                int f = lane + 32 * i;
                float v[8];
#pragma unroll
                for (int u = 0; u < 8; u++) v[u] = H[(size_t)sidx[u] * F + f];
#pragma unroll
                for (int u = 0; u < 8; u++) {
                    if (BN) v[u] = fmaxf(fmaf(v[u], sc[i], sh[i]), 0.f);
                    sum[i] += v[u];
                    ssq[i] = fmaf(v[u], v[u], ssq[i]);
                    mn[i] = fminf(mn[i], v[u]);
                    mx[i] = fmaxf(mx[i], v[u]);
                }
            }
        }
        for (; e < deg; e++) {
            int s = g_srt[st + e];
#pragma unroll
            for (int i = 0; i < FPT; i++) {
                float v = H[(size_t)s * F + lane + 32 * i];
                if (BN) v = fmaxf(fmaf(v, sc[i], sh[i]), 0.f);
                sum[i] += v;
                ssq[i] += v * v;
                mn[i] = fminf(mn[i], v);
                mx[i] = fmaxf(mx[i], v);
            }
        }
        float inv = 1.f / (float)(deg > 1 ? deg : 1);
        float* out = g_agg + (size_t)n * (4 * F);
#pragma unroll
        for (int i = 0; i < FPT; i++) {
            int f = lane + 32 * i;
            float mean = sum[i] * inv;
            float msq = ssq[i] * inv;
            float sd = sqrtf(fmaxf(msq - mean * mean, 0.f) + 1e-5f);
            float lmn = (deg > 0) ? mn[i] : 0.f;
            float lmx = (deg > 0) ? mx[i] : 0.f;
            out[f] = mean;
            out[F + f] = lmn;
            out[2 * F + f] = lmx;
            out[3 * F + f] = sd;
        }
    }
}

// -------- W pre-conversion (also zeroes BN accumulators for the next GEMM) --
template <int K13, int FO, int FOP_>
__global__ void k_wconv(const float* __restrict__ W) {
    int i = blockIdx.x * 256 + threadIdx.x;
    if (blockIdx.x == 0 && threadIdx.x < 128) { g_bnsum[threadIdx.x] = 0.f; g_bnssq[threadIdx.x] = 0.f; }
    if (i >= K13 * FOP_) return;
    int k = i / FOP_;
    int c = i - k * FOP_;
    float v = (c < FO) ? W[(size_t)k * FO + c] : 0.f;
    uint32_t bits = __float_as_uint(v);
    g_Whi[i] = (u16)(bits >> 16);                             // truncation split (exact)
    float lo = v - __uint_as_float(bits & 0xFFFF0000u);
    __nv_bfloat16 lb = __float2bfloat16(lo);
    g_Wlo[i] = *(u16*)&lb;
}

// ---------------- PNA GEMM via mma.sync bf16 (3-term hi/lo split), pipelined --
template <int F, int FO, int FOP_, int NT, int WSTR, bool RELU, bool BNIN, bool STATS>
__global__ void __launch_bounds__(256, 2) k_mma(const float* __restrict__ H,
                                                const float* __restrict__ Bias,
                                                float* __restrict__ OUT) {
    constexpr int K13 = 13 * F;
    constexpr int KT = K13 / 32;
    constexpr int ASTR = 40;
    constexpr int F4 = 4 * F;
    constexpr int WCOLS = NT * 16;
    constexpr int WB = 32 * WSTR;
    __shared__ __align__(16) u16 sAhi[128 * ASTR];
    __shared__ __align__(16) u16 sAlo[128 * ASTR];
    __shared__ __align__(16) u16 sWhi[2][WB];
    __shared__ __align__(16) u16 sWlo[2][WB];
    __shared__ float sS1[128], sS2[128];

    int tid = threadIdx.x;
    int lane = tid & 31;
    int wid = tid >> 5;
    int warpM = wid & 3;
    int warpN = wid >> 2;
    int n0 = blockIdx.x * 128;

    if (tid < 128) {
        int n = n0 + tid;
        sS1[tid] = (n < NN) ? g_s1[n] : 0.f;
        sS2[tid] = (n < NN) ? g_s2[n] : 0.f;
    }
    if (FOP_ < WCOLS) {
        for (int i = tid; i < 32 * (WCOLS - FOP_); i += 256) {
            int kr = i / (WCOLS - FOP_);
            int c = FOP_ + i % (WCOLS - FOP_);
            sWhi[0][kr * WSTR + c] = 0; sWhi[1][kr * WSTR + c] = 0;
            sWlo[0][kr * WSTR + c] = 0; sWlo[1][kr * WSTR + c] = 0;
        }
    }

    uint32_t aAhi = smem_u32(sAhi), aAlo = smem_u32(sAlo);
    uint32_t aWhi0 = smem_u32(&sWhi[0][0]), aWlo0 = smem_u32(&sWlo[0][0]);

    float acc[2][NT][4];
#pragma unroll
    for (int m = 0; m < 2; m++)
#pragma unroll
        for (int n = 0; n < NT; n++)
#pragma unroll
            for (int j = 0; j < 4; j++) acc[m][n][j] = 0.f;

    int q = lane >> 3, r = lane & 7;
    uint32_t aoff = (uint32_t)((warpM * 32 + (q & 1) * 8 + r) * ASTR + (q >> 1) * 8) * 2;
    uint32_t boff = (uint32_t)(((q & 1) * 8 + r) * WSTR + warpN * NT * 8 + (q >> 1) * 8) * 2;

    float2 pv[8];

    auto loadA = [&](int t) {
        int kb = t * 32;
#pragma unroll
        for (int p = 0; p < 8; p++) {
            int idx = tid + p * 256;
            int row = idx >> 4;
            int kp = idx & 15;
            int n = n0 + row;
            int k = kb + 2 * kp;
            float2 v = make_float2(0.f, 0.f);
            if (n < NN) {
                if (k < F) {
                    v = *(const float2*)&H[(size_t)n * F + k];
                    if (BNIN) {
                        float2 sc2 = *(const float2*)&g_scale[k];
                        float2 sh2 = *(const float2*)&g_shift[k];
                        v.x = fmaxf(fmaf(v.x, sc2.x, sh2.x), 0.f);
                        v.y = fmaxf(fmaf(v.y, sc2.y, sh2.y), 0.f);
                    }
                } else {
                    int j = k - F;
                    float sc;
                    int jj;
                    if (j < F4)          { sc = 1.f;      jj = j; }
                    else if (j < 2 * F4) { sc = sS1[row]; jj = j - F4; }
                    else                 { sc = sS2[row]; jj = j - 2 * F4; }
                    float2 a = *(const float2*)&g_agg[(size_t)n * F4 + jj];
                    v.x = a.x * sc;
                    v.y = a.y * sc;
                }
            }
            pv[p] = v;
        }
    };
    auto storeA = [&]() {
#pragma unroll
        for (int p = 0; p < 8; p++) {
            int idx = tid + p * 256;
            int row = idx >> 4;
            int kp = idx & 15;
            float2 v = pv[p];
            uint32_t xi = __float_as_uint(v.x), yi = __float_as_uint(v.y);
            uint32_t hip = __byte_perm(xi, yi, 0x7632);
            float lx = v.x - __uint_as_float(xi & 0xFFFF0000u);
            float ly = v.y - __uint_as_float(yi & 0xFFFF0000u);
            __nv_bfloat162 lop = __floats2bfloat162_rn(lx, ly);
            *(uint32_t*)&sAhi[row * ASTR + 2 * kp] = hip;
            *(uint32_t*)&sAlo[row * ASTR + 2 * kp] = *(uint32_t*)&lop;
        }
    };
    auto cpW = [&](int t, int buf) {
        int kb = t * 32;
        constexpr int NU4 = 32 * FOP_ / 8;
        for (int i = tid; i < NU4; i += 256) {
            int kr = i / (FOP_ / 8);
            int ch = i - kr * (FOP_ / 8);
            uint32_t doff = (uint32_t)(kr * WSTR + ch * 8) * 2;
            size_t soff = (size_t)(kb + kr) * FOP_ + ch * 8;
            cpa16(aWhi0 + buf * (WB * 2) + doff, &g_Whi[soff]);
            cpa16(aWlo0 + buf * (WB * 2) + doff, &g_Wlo[soff]);
        }
    };

    loadA(0);
    cpW(0, 0);
    CPA_COMMIT();
    storeA();
    CPA_WAIT0();
    __syncthreads();

    for (int t = 0; t < KT; t++) {
        int cur = t & 1;
        if (t + 1 < KT) {
            loadA(t + 1);
            cpW(t + 1, cur ^ 1);
            CPA_COMMIT();
        }
        uint32_t aW_hi = aWhi0 + cur * (WB * 2);
        uint32_t aW_lo = aWlo0 + cur * (WB * 2);
#pragma unroll
        for (int ks = 0; ks < 32; ks += 16) {
            uint32_t ah[2][4], al[2][4];
            ldm_x4(ah[0], aAhi + aoff + 2 * ks);
            ldm_x4(ah[1], aAhi + aoff + 2 * ks + 16 * ASTR * 2);
            ldm_x4(al[0], aAlo + aoff + 2 * ks);
            ldm_x4(al[1], aAlo + aoff + 2 * ks + 16 * ASTR * 2);
            uint32_t bh[NT][2], bl[NT][2];
#pragma unroll
            for (int p2 = 0; p2 < NT / 2; p2++) {
                uint32_t r4[4];
                ldm_x4t(r4, aW_hi + boff + 2 * (ks * WSTR) + p2 * 32);
                bh[2 * p2][0] = r4[0]; bh[2 * p2][1] = r4[1];
                bh[2 * p2 + 1][0] = r4[2]; bh[2 * p2 + 1][1] = r4[3];
                ldm_x4t(r4, aW_lo + boff + 2 * (ks * WSTR) + p2 * 32);
                bl[2 * p2][0] = r4[0]; bl[2 * p2][1] = r4[1];
                bl[2 * p2 + 1][0] = r4[2]; bl[2 * p2 + 1][1] = r4[3];
            }
#pragma unroll
            for (int m = 0; m < 2; m++)
#pragma unroll
                for (int nt2 = 0; nt2 < NT; nt2++) {
                    mma_bf16(acc[m][nt2], ah[m], bh[nt2]);
                    mma_bf16(acc[m][nt2], al[m], bh[nt2]);
                    mma_bf16(acc[m][nt2], ah[m], bl[nt2]);
                }
        }
        __syncthreads();
        if (t + 1 < KT) storeA();
        CPA_WAIT0();
        __syncthreads();
    }
    // ---- epilogue (+ optional BN stats) ----
    int gi = lane >> 2, ti = lane & 3;
    float cs[NT][2], cq[NT][2];
    if (STATS) {
#pragma unroll
        for (int n = 0; n < NT; n++) { cs[n][0] = 0.f; cs[n][1] = 0.f; cq[n][0] = 0.f; cq[n][1] = 0.f; }
    }
#pragma unroll
    for (int m = 0; m < 2; m++) {
        int row0 = n0 + warpM * 32 + m * 16 + gi;
#pragma unroll
        for (int nt2 = 0; nt2 < NT; nt2++) {
            int col = warpN * NT * 8 + nt2 * 8 + ti * 2;
            if (col < FO) {
                float b0v = Bias[col], b1v = Bias[col + 1];
                if (row0 < NN) {
                    float r0v = acc[m][nt2][0] + b0v;
                    float r1v = acc[m][nt2][1] + b1v;
                    if (RELU) { r0v = fmaxf(r0v, 0.f); r1v = fmaxf(r1v, 0.f); }
                    OUT[(size_t)row0 * FO + col] = r0v;
                    OUT[(size_t)row0 * FO + col + 1] = r1v;
                    if (STATS) {
                        cs[nt2][0] += r0v; cq[nt2][0] += r0v * r0v;
                        cs[nt2][1] += r1v; cq[nt2][1] += r1v * r1v;
                    }
                }
                if (row0 + 8 < NN) {
                    float r2v = acc[m][nt2][2] + b0v;
                    float r3v = acc[m][nt2][3] + b1v;
                    if (RELU) { r2v = fmaxf(r2v, 0.f); r3v = fmaxf(r3v, 0.f); }
                    OUT[(size_t)(row0 + 8) * FO + col] = r2v;
                    OUT[(size_t)(row0 + 8) * FO + col + 1] = r3v;
                    if (STATS) {
                        cs[nt2][0] += r2v; cq[nt2][0] += r2v * r2v;
                        cs[nt2][1] += r3v; cq[nt2][1] += r3v * r3v;
                    }
                }
            }
        }
    }
    if (STATS) {
        __syncthreads();
        for (int i = tid; i < FO; i += 256) { sS1[i] = 0.f; sS2[i] = 0.f; }
        __syncthreads();
#pragma unroll
        for (int nt2 = 0; nt2 < NT; nt2++)
#pragma unroll
            for (int j = 0; j < 2; j++) {
                float v = cs[nt2][j], qv = cq[nt2][j];
                v += __shfl_xor_sync(0xFFFFFFFFu, v, 4);
                qv += __shfl_xor_sync(0xFFFFFFFFu, qv, 4);
                v += __shfl_xor_sync(0xFFFFFFFFu, v, 8);
                qv += __shfl_xor_sync(0xFFFFFFFFu, qv, 8);
                v += __shfl_xor_sync(0xFFFFFFFFu, v, 16);
                qv += __shfl_xor_sync(0xFFFFFFFFu, qv, 16);
                if (gi == 0) {
                    int col = warpN * NT * 8 + nt2 * 8 + ti * 2 + j;
                    if (col < FO) {
                        atomicAdd(&sS1[col], v);
                        atomicAdd(&sS2[col], qv);
                    }
                }
            }
        __syncthreads();
        for (int i = tid; i < FO; i += 256) {
            atomicAdd(&g_bnsum[i], sS1[i]);
            atomicAdd(&g_bnssq[i], sS2[i]);
        }
    }
}

// ---------------- BN finalize ----------------
template <int C>
__global__ void k_bnfin(const float* __restrict__ g, const float* __restrict__ be) {
    int c = threadIdx.x;
    if (c < C) {
        float mu = g_bnsum[c] / (float)NN;
        float var = g_bnssq[c] / (float)NN - mu * mu;
        float rs = rsqrtf(var + 1e-5f);
        float sc = g[c] * rs;
        g_scale[c] = sc;
        g_shift[c] = be[c] - mu * sc;
    }
}

// ---------------- pooling (smem-staged) + head ----------------
__global__ void k_pool(const float* __restrict__ h, const int* __restrict__ batch) {
    __shared__ float sz[NGR * 20];
    __shared__ int scnt[NGR];
    int tid = threadIdx.x;
    for (int i = tid; i < NGR * 20; i += 256) sz[i] = 0.f;
    for (int i = tid; i < NGR; i += 256) scnt[i] = 0;
    __syncthreads();
    int i = blockIdx.x * 256 + tid;
    if (i < NN) {
        int g = batch[i];
        atomicAdd(&scnt[g], 1);
        const float* row = h + (size_t)i * 20;
#pragma unroll
        for (int c = 0; c < 20; c++) {
            float v = row[c] * g_scale[c] + g_shift[c];
            atomicAdd(&sz[g * 20 + c], v);
        }
    }
    __syncthreads();
    for (int i2 = tid; i2 < NGR * 20; i2 += 256)
        if (sz[i2] != 0.f) atomicAdd(&g_zsum[i2], sz[i2]);
    for (int i2 = tid; i2 < NGR; i2 += 256)
        if (scnt[i2]) atomicAdd(&g_gcnt[i2], scnt[i2]);
}

__global__ void k_final(const float* __restrict__ wl, const float* __restrict__ bl,
                        float* __restrict__ out, int out_size) {
    int g = threadIdx.x;
    if (g >= NGR) return;
    float inv = 1.f / fmaxf((float)g_gcnt[g], 1.f);
    float z[20];
#pragma unroll
    for (int c = 0; c < 20; c++) z[c] = g_zsum[g * 20 + c] * inv;
    float lo[11];
    float m = -3.4e38f;
#pragma unroll
    for (int o = 0; o < 11; o++) {
        float a = bl[o];
#pragma unroll
        for (int c = 0; c < 20; c++) a += z[c] * wl[c * 11 + o];
        lo[o] = a;
        m = fmaxf(m, a);
    }
    float ssum = 0.f;
#pragma unroll
    for (int o = 0; o < 11; o++) { lo[o] = expf(lo[o] - m); ssum += lo[o]; }
    float isum = 1.f / ssum;
#pragma unroll
    for (int o = 0; o < 11; o++) {
        int idx = g * 11 + o;
        if (idx < out_size) out[idx] = lo[o] * isum;
    }
#pragma unroll
    for (int c = 0; c < 20; c++) {
        int idx = NGR * 11 + g * 20 + c;
        if (idx < out_size) out[idx] = z[c];
    }
}

// ---------------- launcher ----------------
extern "C" void kernel_launch(void* const* d_in, const int* in_sizes, int n_in,
                              void* d_out, int out_size) {
    const float* x = (const float*)d_in[0];
    const int* ei = (const int*)d_in[1];
    const int* src = ei;
    const int* dst = ei + NE;
    const int* batch = (const int*)d_in[2];
    const float* w0 = (const float*)d_in[3];  const float* b0 = (const float*)d_in[4];
    const float* w1 = (const float*)d_in[5];  const float* b1 = (const float*)d_in[6];
    const float* w2 = (const float*)d_in[7];  const float* b2 = (const float*)d_in[8];
    const float* w3 = (const float*)d_in[9];  const float* b3 = (const float*)d_in[10];
    const float* g0 = (const float*)d_in[11]; const float* be0 = (const float*)d_in[12];
    const float* g1 = (const float*)d_in[13]; const float* be1 = (const float*)d_in[14];
    const float* g2 = (const float*)d_in[15]; const float* be2 = (const float*)d_in[16];
    const float* wl = (const float*)d_in[17]; const float* bl = (const float*)d_in[18];

    void* pA = 0; void* pB = 0; void* pCnt = 0; void* pZ = 0; void* pG = 0;
    cudaGetSymbolAddress(&pA, g_hA);
    cudaGetSymbolAddress(&pB, g_hB);
    cudaGetSymbolAddress(&pCnt, g_cnt);
    cudaGetSymbolAddress(&pZ, g_zsum);
    cudaGetSymbolAddress(&pG, g_gcnt);
    float* hA = (float*)pA;
    float* hB = (float*)pB;

    const int GB_E = (NE + 255) / 256;
    const int GB_N = (NN + 255) / 256;
    const int GB_M = (NN + 127) / 128;

    cudaMemsetAsync(pCnt, 0, NN * sizeof(int));
    cudaMemsetAsync(pZ, 0, NGR * 20 * sizeof(float));
    cudaMemsetAsync(pG, 0, NGR * sizeof(int));
    k_count<<<GB_E, 256>>>(dst);
    k_scan1<<<GB_N, 256>>>();
    k_scan2<<<1, 512>>>();
    k_scan3<<<GB_N, 256>>>();
    k_scatter<<<GB_E, 256>>>(src, dst);

    // layer 0: 64 -> 96, BN stats fused in epilogue
    k_agg<64, false><<<(NN * 32 + 255) / 256, 256>>>(x);
    k_wconv<832, 96, 96><<<(832 * 96 + 255) / 256, 256>>>(w0);
    k_mma<64, 96, 96, 6, 104, false, false, true><<<GB_M, 256>>>(x, b0, hA);
    k_bnfin<96><<<1, 96>>>(g0, be0);

    // layer 1: 96 -> 64; BN0 applied on the fly in agg + A-build
    k_agg<96, true><<<(NN * 32 + 255) / 256, 256>>>(hA);
    k_wconv<1248, 64, 64><<<(1248 * 64 + 255) / 256, 256>>>(w1);
    k_mma<96, 64, 64, 4, 72, false, true, true><<<GB_M, 256>>>(hA, b1, hB);
    k_bnfin<64><<<1, 64>>>(g1, be1);

    // layer 2: 64 -> 32; BN1 applied on the fly; relu in epilogue
    k_agg<64, true><<<(NN * 32 + 255) / 256, 256>>>(hB);
    k_wconv<832, 32, 32><<<(832 * 32 + 255) / 256, 256>>>(w2);
    k_mma<64, 32, 32, 2, 40, true, true, false><<<GB_M, 256>>>(hB, b2, hA);

    // layer 3: 32 -> 20; BN2 stats fused; affine applied in pooling
    k_agg<32, false><<<(NN * 32 + 255) / 256, 256>>>(hA);
    k_wconv<416, 20, 24><<<(416 * 24 + 255) / 256, 256>>>(w3);
    k_mma<32, 20, 24, 2, 40, false, false, true><<<GB_M, 256>>>(hA, b3, hB);
    k_bnfin<20><<<1, 32>>>(g2, be2);

    k_pool<<<GB_N, 256>>>(hB, batch);
    k_final<<<1, 64>>>(wl, bl, (float*)d_out, out_size);
}